// round 12
// baseline (speedup 1.0000x reference)
#include <cuda_runtime.h>
#include <math.h>
#include <stdint.h>

#define B_  512
#define T_  24
#define V_  8000
#define E_  300
#define M_  30
#define H_  330
#define NP  352            // padded n-columns (11 warps)
#define NSTEPS 8
#define DT_ 0.875f         // 7/8
#define VP  8192           // padded V for W_d2T
#define NP1 320            // padded N for d1 stage

#define CLUSTER_N 8
#define K_CH 33            // k-rows per chunk (330 = 10 * 33)
#define NCHUNK 10
#define CHUNK_FLOATS (K_CH * NP)          // 11616
#define CHUNK_BYTES  (CHUNK_FLOATS * 4)   // 46464
#define NBUF 3

// dynamic smem layout (float offsets)
#define SM_WBUF 0
#define SM_HS   (NBUF * CHUNK_FLOATS)         // 34848
#define SM_ACC  (SM_HS  + NP * 4)
#define SM_YS   (SM_ACC + NP * 4)
#define SM_AS   (SM_YS  + NP * 4)
#define SM_BS   (SM_AS  + NP * 4)
#define SM_G1   (SM_BS  + NP * 4)
#define SM_G2   (SM_G1  + 96 * 4)
#define SM_MBAR (SM_G2  + 96 * 4)             // 6 mbarriers (8B each)
#define SMEM_TOTAL_SEQ ((SM_MBAR * 4) + 64)

// ---------------- device scratch (static, no allocation) ----------------
__device__ float g_Wseq[4 * 330 * NP];   // [mat(W1,W2,W3,Wu)][k<330][n<352]
__device__ float g_WihT[E_ * 96];        // [e<300][g<90]
__device__ float g_WhhT[M_ * 96];        // [m<30][g<90]
__device__ float g_Wd1T[E_ * NP1];       // [k<300][n<300]
__device__ float g_Wd2T[E_ * VP];        // [n<300][v<8000]
__device__ float g_WembT[V_ * E_];       // [v][e]
__device__ float g_bu_pad[NP];
__device__ float g_bd1_pad[NP1];
__device__ int   g_len[B_];
__device__ float g_gall[(size_t)B_ * T_ * E_];        // [b][t][e]
__device__ float g_hemb[(size_t)(T_ - 1) * B_ * E_];  // [kk][b][e]
__device__ float g_d1[(size_t)(T_ - 1) * B_ * E_];    // [kk][b][e]

// ---------------- PTX helpers ----------------
__device__ __forceinline__ uint32_t smem_u32(const void* p) {
    uint32_t a;
    asm("{ .reg .u64 t; cvta.to.shared.u64 t, %1; cvt.u32.u64 %0, t; }" : "=r"(a) : "l"(p));
    return a;
}
__device__ __forceinline__ uint32_t ctarank() {
    uint32_t r; asm("mov.u32 %0, %%cluster_ctarank;" : "=r"(r)); return r;
}
#define MBARRIER_INIT(a, c) \
    asm volatile("mbarrier.init.shared.b64 [%0], %1;" :: "r"(a), "r"((uint32_t)(c)) : "memory")
#define MBARRIER_EXPECT_TX(a, tx) \
    asm volatile("mbarrier.arrive.expect_tx.shared.b64 _, [%0], %1;" :: "r"(a), "r"((uint32_t)(tx)) : "memory")
#define MBARRIER_ARRIVE_CLUSTER(a, rk) \
    asm volatile("{ .reg .b32 ra; mapa.shared::cluster.u32 ra, %0, %1;" \
                 " mbarrier.arrive.shared::cluster.b64 _, [ra]; }" \
                 :: "r"(a), "r"((uint32_t)(rk)) : "memory")
#define MBARRIER_WAIT_PARITY(a, p) do { \
    asm volatile("{ .reg .pred P1; WL%=:" \
                 " mbarrier.try_wait.parity.acquire.cta.shared::cta.b64 P1, [%0], %1, 0x989680;" \
                 " @P1 bra.uni WD%=; bra.uni WL%=; WD%=: }" \
                 :: "r"(a), "r"((uint32_t)(p)) : "memory"); } while (0)
#define MBARRIER_WAIT_PARITY_RELAXED(a, p) do { \
    asm volatile("{ .reg .pred P1; WL%=:" \
                 " mbarrier.try_wait.parity.relaxed.cta.shared::cta.b64 P1, [%0], %1, 0x989680;" \
                 " @P1 bra.uni WD%=; bra.uni WL%=; WD%=: }" \
                 :: "r"(a), "r"((uint32_t)(p)) : "memory"); } while (0)
#define CBAR() asm volatile("bar.sync 1, 352;" ::: "memory")
#define CLUSTER_SYNC() do { \
    asm volatile("barrier.cluster.arrive.aligned;" ::: "memory"); \
    asm volatile("barrier.cluster.wait.aligned;" ::: "memory"); } while (0)

// ---------------- lengths normalization (int32 vs int64 auto-detect) ----------------
__global__ void prep_len(const int* __restrict__ Lraw) {
    int b = blockIdx.x * blockDim.x + threadIdx.x;
    if (b >= B_) return;
    int is64 = (Lraw[1] == 0);
    g_len[b] = is64 ? Lraw[2 * b] : Lraw[b];
}

// ---------------- fused weight prep ----------------
__global__ void prep_all(const float* __restrict__ W1, const float* __restrict__ W2,
                         const float* __restrict__ W3, const float* __restrict__ Wu,
                         const float* __restrict__ bu,
                         const float* __restrict__ Wih, const float* __restrict__ Whh,
                         const float* __restrict__ Wd1, const float* __restrict__ bd1) {
    int i = blockIdx.x * blockDim.x + threadIdx.x;
    if (i < 4 * 330 * NP) {
        int mat = i / (330 * NP);
        int r = i - mat * (330 * NP);
        int k = r / NP, n = r % NP;
        float v = 0.f;
        if (mat == 0)      { if (n < H_) v = W1[n * H_ + k]; }
        else if (mat == 1) { if (n < H_) v = W2[n * H_ + k]; }
        else if (mat == 2) { if (n < H_) v = W3[n * H_ + k]; }
        else               { if (n < E_) v = Wu[n * H_ + k]; }
        g_Wseq[i] = v;
    }
    if (i < E_ * 96) {
        int e = i / 96, g = i % 96;
        g_WihT[i] = (g < 90) ? Wih[g * E_ + e] : 0.f;
    }
    if (i < M_ * 96) {
        int m = i / 96, g = i % 96;
        g_WhhT[i] = (g < 90) ? Whh[g * M_ + m] : 0.f;
    }
    if (i < E_ * NP1) {
        int k = i / NP1, n = i % NP1;
        g_Wd1T[i] = (n < E_) ? Wd1[n * E_ + k] : 0.f;
    }
    if (i < NP)  g_bu_pad[i]  = (i < E_) ? bu[i]  : 0.f;
    if (i < NP1) g_bd1_pad[i] = (i < E_) ? bd1[i] : 0.f;
}

__global__ void prep_wd2(const float* __restrict__ Wd2) {
    int i = blockIdx.x * blockDim.x + threadIdx.x;
    if (i >= E_ * VP) return;
    int n = i / VP, v = i % VP;
    g_Wd2T[i] = (v < V_) ? Wd2[v * E_ + n] : 0.f;
}

__global__ void prep_wemb(const float* __restrict__ Wemb) {
    int i = blockIdx.x * blockDim.x + threadIdx.x;
    if (i >= V_ * E_) return;
    int v = i / E_, e = i % E_;
    g_WembT[i] = Wemb[e * V_ + v];
}

// ---------------- sparse embedding (deterministic prefix-scan compaction) ----------------
__global__ void __launch_bounds__(256) embed_kernel(const float* __restrict__ codes,
                                                    const float* __restrict__ bemb) {
    __shared__ int idx[1024];
    __shared__ int cnts[256];
    __shared__ int total;
    int blk = blockIdx.x;               // blk = b*T_ + t
    int t = threadIdx.x;
    const float* crow = codes + (size_t)blk * V_;
    int base = t * 32;
    int c = 0;
#pragma unroll 4
    for (int j = 0; j < 32; j++) {
        int v = base + j;
        if (v < V_ && crow[v] != 0.f) c++;
    }
    cnts[t] = c;
    __syncthreads();
    for (int off = 1; off < 256; off <<= 1) {
        int val = cnts[t];
        int add = (t >= off) ? cnts[t - off] : 0;
        __syncthreads();
        cnts[t] = val + add;
        __syncthreads();
    }
    int p = cnts[t] - c;
    for (int j = 0; j < 32; j++) {
        int v = base + j;
        if (v < V_ && crow[v] != 0.f) {
            if (p < 1024) idx[p] = v;
            p++;
        }
    }
    if (t == 255) total = cnts[255];
    __syncthreads();
    int n = total > 1024 ? 1024 : total;
    for (int e = t; e < E_; e += 256) {
        float acc = bemb[e];
        for (int j = 0; j < n; j++) acc += g_WembT[idx[j] * E_ + e];
        g_gall[(size_t)blk * E_ + e] = acc;
    }
}

// ---------------- seq kernel: warp-specialized TMA-multicast pipeline ----------------
__device__ __forceinline__ float sigf(float x) { return 1.f / (1.f + expf(-x)); }

// consumer: one matmul stage consuming NCHUNK chunks from the ring
template <bool TANH, bool BIAS>
__device__ __forceinline__ void stageC(const float* __restrict__ sw,   // smem wbuf base
                                       uint32_t mbf, uint32_t mbe,
                                       int& buf, int* phf,
                                       const float4* __restrict__ src,
                                       float4* __restrict__ dst,
                                       const float* __restrict__ bias,
                                       int n, int lane0) {
    float a0 = 0.f, a1 = 0.f, a2 = 0.f, a3 = 0.f;
#pragma unroll 1
    for (int c = 0; c < NCHUNK; c++) {
        MBARRIER_WAIT_PARITY(mbf + buf * 8, phf[buf]);
        phf[buf] ^= 1;
        const float* wb = sw + buf * CHUNK_FLOATS + n;
        const float4* xp = src + c * K_CH;
#pragma unroll 3
        for (int kc = 0; kc < K_CH; kc++) {
            float w = wb[kc * NP];
            float4 x = xp[kc];
            a0 = fmaf(w, x.x, a0);
            a1 = fmaf(w, x.y, a1);
            a2 = fmaf(w, x.z, a2);
            a3 = fmaf(w, x.w, a3);
        }
        if (lane0) { MBARRIER_ARRIVE_CLUSTER(mbe + buf * 8, 0); }
        buf = (buf < NBUF - 1) ? buf + 1 : 0;
    }
    if (BIAS) { float bv = bias[n]; a0 += bv; a1 += bv; a2 += bv; a3 += bv; }
    if (TANH) { a0 = tanhf(a0); a1 = tanhf(a1); a2 = tanhf(a2); a3 = tanhf(a3); }
    dst[n] = make_float4(a0, a1, a2, a3);
    CBAR();
}

// producer: push the NCHUNK chunks of one matrix through the ring
__device__ __forceinline__ void prodM(int mat, int& buf, int* pe, int* pf,
                                      uint32_t rank, uint32_t sw_a,
                                      uint32_t mbf, uint32_t mbe) {
    const char* gsrc = (const char*)(g_Wseq + (size_t)mat * 330 * NP);
#pragma unroll 1
    for (int c = 0; c < NCHUNK; c++) {
        uint32_t fullb = mbf + buf * 8;
        if (rank == 0) {
            MBARRIER_WAIT_PARITY_RELAXED(mbe + buf * 8, pe[buf]);
            pe[buf] ^= 1;
            MBARRIER_EXPECT_TX(fullb, CHUNK_BYTES);
            asm volatile(
                "cp.async.bulk.shared::cluster.global.mbarrier::complete_tx::bytes"
                ".multicast::cluster [%0], [%1], %2, [%3], %4;"
                :: "r"(sw_a + buf * CHUNK_BYTES),
                   "l"(gsrc + (size_t)c * CHUNK_BYTES),
                   "r"((uint32_t)CHUNK_BYTES), "r"(fullb),
                   "h"((unsigned short)0xFF)
                : "memory");
        } else {
            MBARRIER_EXPECT_TX(fullb, CHUNK_BYTES);
            MBARRIER_WAIT_PARITY_RELAXED(fullb, pf[buf]);
            pf[buf] ^= 1;
        }
        buf = (buf < NBUF - 1) ? buf + 1 : 0;
    }
}

__global__ void __launch_bounds__(384, 1) __cluster_dims__(CLUSTER_N, 1, 1)
seq_kernel(const float* __restrict__ b_ih, const float* __restrict__ b_hh) {
    extern __shared__ float smem[];
    float4* Hs  = (float4*)(smem + SM_HS);
    float4* ACC = (float4*)(smem + SM_ACC);
    float4* Ys  = (float4*)(smem + SM_YS);
    float4* As  = (float4*)(smem + SM_AS);
    float4* Bs  = (float4*)(smem + SM_BS);
    float4* G1  = (float4*)(smem + SM_G1);
    float4* G2  = (float4*)(smem + SM_G2);
    const float* sw = smem + SM_WBUF;
    uint32_t sw_a = smem_u32(smem);
    uint32_t mbf = smem_u32(smem + SM_MBAR);          // full[3]
    uint32_t mbe = mbf + NBUF * 8;                    // empty[3] (rank0 authoritative)

    int tid = threadIdx.x;
    uint32_t rank = ctarank();
    int b0 = blockIdx.x * 4;

    if (tid == 0) {
        for (int i = 0; i < NBUF; i++) {
            MBARRIER_INIT(mbf + i * 8, 1);
            MBARRIER_INIT(mbe + i * 8, 11 * CLUSTER_N);
        }
    }
    __syncthreads();
    CLUSTER_SYNC();

    if (tid >= NP) {
        // ---------------- producer warp ----------------
        if (tid == NP) {
            int buf = 0;
            int pe[NBUF] = {1, 1, 1};
            int pf[NBUF] = {0, 0, 0};
            for (int k = 1; k < T_; k++) {
                for (int s = 0; s < NSTEPS; s++)
                    for (int f = 0; f < 4; f++) {
                        prodM(0, buf, pe, pf, rank, sw_a, mbf, mbe);
                        prodM(1, buf, pe, pf, rank, sw_a, mbf, mbe);
                        prodM(2, buf, pe, pf, rank, sw_a, mbf, mbe);
                    }
                prodM(3, buf, pe, pf, rank, sw_a, mbf, mbe);
            }
        }
    } else {
        // ---------------- consumer threads (352) ----------------
        int n = tid;
        int lane0 = ((tid & 31) == 0);
        int buf = 0;
        int phf[NBUF] = {0, 0, 0};

        // h0 = [zeros(M), g_all[:,0,:]]
        {
            float4 h = make_float4(0.f, 0.f, 0.f, 0.f);
            if (n >= M_ && n < H_) {
                int e = n - M_;
                h.x = g_gall[((size_t)(b0 + 0) * T_ + 0) * E_ + e];
                h.y = g_gall[((size_t)(b0 + 1) * T_ + 0) * E_ + e];
                h.z = g_gall[((size_t)(b0 + 2) * T_ + 0) * E_ + e];
                h.w = g_gall[((size_t)(b0 + 3) * T_ + 0) * E_ + e];
            }
            Hs[n] = h;
            CBAR();
        }

        for (int k = 1; k < T_; k++) {
            for (int s = 0; s < NSTEPS; s++) {
                // --- k1 = f(Hs) ---
                stageC<true, false>(sw, mbf, mbe, buf, phf, Hs, As, nullptr, n, lane0);
                stageC<true, false>(sw, mbf, mbe, buf, phf, As, Bs, nullptr, n, lane0);
                stageC<true, false>(sw, mbf, mbe, buf, phf, Bs, As, nullptr, n, lane0);
                {
                    float4 a = As[n], h = Hs[n];
                    ACC[n] = a;
                    Ys[n] = make_float4(h.x + 0.5f * DT_ * a.x, h.y + 0.5f * DT_ * a.y,
                                        h.z + 0.5f * DT_ * a.z, h.w + 0.5f * DT_ * a.w);
                    CBAR();
                }
                // --- k2 = f(Ys) ---
                stageC<true, false>(sw, mbf, mbe, buf, phf, Ys, As, nullptr, n, lane0);
                stageC<true, false>(sw, mbf, mbe, buf, phf, As, Bs, nullptr, n, lane0);
                stageC<true, false>(sw, mbf, mbe, buf, phf, Bs, As, nullptr, n, lane0);
                {
                    float4 a = As[n], h = Hs[n], c = ACC[n];
                    ACC[n] = make_float4(c.x + 2.f * a.x, c.y + 2.f * a.y,
                                         c.z + 2.f * a.z, c.w + 2.f * a.w);
                    Ys[n] = make_float4(h.x + 0.5f * DT_ * a.x, h.y + 0.5f * DT_ * a.y,
                                        h.z + 0.5f * DT_ * a.z, h.w + 0.5f * DT_ * a.w);
                    CBAR();
                }
                // --- k3 = f(Ys) ---
                stageC<true, false>(sw, mbf, mbe, buf, phf, Ys, As, nullptr, n, lane0);
                stageC<true, false>(sw, mbf, mbe, buf, phf, As, Bs, nullptr, n, lane0);
                stageC<true, false>(sw, mbf, mbe, buf, phf, Bs, As, nullptr, n, lane0);
                {
                    float4 a = As[n], h = Hs[n], c = ACC[n];
                    ACC[n] = make_float4(c.x + 2.f * a.x, c.y + 2.f * a.y,
                                         c.z + 2.f * a.z, c.w + 2.f * a.w);
                    Ys[n] = make_float4(h.x + DT_ * a.x, h.y + DT_ * a.y,
                                        h.z + DT_ * a.z, h.w + DT_ * a.w);
                    CBAR();
                }
                // --- k4 = f(Ys) ---
                stageC<true, false>(sw, mbf, mbe, buf, phf, Ys, As, nullptr, n, lane0);
                stageC<true, false>(sw, mbf, mbe, buf, phf, As, Bs, nullptr, n, lane0);
                stageC<true, false>(sw, mbf, mbe, buf, phf, Bs, As, nullptr, n, lane0);
                {
                    const float c6 = DT_ / 6.f;
                    float4 a = As[n], h = Hs[n], c = ACC[n];
                    Hs[n] = make_float4(h.x + c6 * (c.x + a.x), h.y + c6 * (c.y + a.y),
                                        h.z + c6 * (c.z + a.z), h.w + c6 * (c.w + a.w));
                    CBAR();
                }
            }

            // ---- dump h_emb; build cin = [h_mem, g_k] ----
            if (n < E_) {
                float4 v = Hs[M_ + n];
                size_t base = ((size_t)(k - 1) * B_ + b0) * E_ + n;
                g_hemb[base]          = v.x;
                g_hemb[base + E_]     = v.y;
                g_hemb[base + 2 * E_] = v.z;
                g_hemb[base + 3 * E_] = v.w;
            }
            {
                float4 c = make_float4(0.f, 0.f, 0.f, 0.f);
                if (n < M_) c = Hs[n];
                else if (n < H_) {
                    int e = n - M_;
                    c.x = g_gall[((size_t)(b0 + 0) * T_ + k) * E_ + e];
                    c.y = g_gall[((size_t)(b0 + 1) * T_ + k) * E_ + e];
                    c.z = g_gall[((size_t)(b0 + 2) * T_ + k) * E_ + e];
                    c.w = g_gall[((size_t)(b0 + 3) * T_ + k) * E_ + e];
                }
                Ys[n] = c;
                CBAR();
            }

            // ---- x = cin @ W_u^T + b_u  -> As ----
            stageC<false, true>(sw, mbf, mbe, buf, phf, Ys, As, g_bu_pad, n, lane0);

            // ---- GRU gates ----
            if (tid < 96) {
                int g = tid;
                float bb = (g < 90) ? b_ih[g] : 0.f;
                float4 a = make_float4(bb, bb, bb, bb);
#pragma unroll 4
                for (int e = 0; e < E_; e++) {
                    float w = g_WihT[e * 96 + g];
                    float4 x = As[e];
                    a.x = fmaf(w, x.x, a.x); a.y = fmaf(w, x.y, a.y);
                    a.z = fmaf(w, x.z, a.z); a.w = fmaf(w, x.w, a.w);
                }
                G1[g] = a;
            } else if (tid < 192) {
                int g = tid - 96;
                float bb = (g < 90) ? b_hh[g] : 0.f;
                float4 a = make_float4(bb, bb, bb, bb);
#pragma unroll
                for (int m = 0; m < M_; m++) {
                    float w = g_WhhT[m * 96 + g];
                    float4 x = Hs[m];
                    a.x = fmaf(w, x.x, a.x); a.y = fmaf(w, x.y, a.y);
                    a.z = fmaf(w, x.z, a.z); a.w = fmaf(w, x.w, a.w);
                }
                G2[g] = a;
            }
            CBAR();

            if (tid < M_) {
                int m = tid;
                float4 xr = G1[m],          hr = G2[m];
                float4 xz = G1[M_ + m],     hz = G2[M_ + m];
                float4 xn = G1[2 * M_ + m], hn = G2[2 * M_ + m];
                float4 ho = Hs[m];
                float4 hv;
                { float r = sigf(xr.x + hr.x), z = sigf(xz.x + hz.x);
                  float t = tanhf(xn.x + r * hn.x); hv.x = (1.f - z) * t + z * ho.x; }
                { float r = sigf(xr.y + hr.y), z = sigf(xz.y + hz.y);
                  float t = tanhf(xn.y + r * hn.y); hv.y = (1.f - z) * t + z * ho.y; }
                { float r = sigf(xr.z + hr.z), z = sigf(xz.z + hz.z);
                  float t = tanhf(xn.z + r * hn.z); hv.z = (1.f - z) * t + z * ho.z; }
                { float r = sigf(xr.w + hr.w), z = sigf(xz.w + hz.w);
                  float t = tanhf(xn.w + r * hn.w); hv.w = (1.f - z) * t + z * ho.w; }
                Hs[m] = hv;
            }
            CBAR();
        }
    }
    CLUSTER_SYNC();
}

// ---------------- decoder stage 1: d1 = leaky_relu(hemb @ W_d1^T + b_d1) ----------------
__global__ void __launch_bounds__(NP1) d1_kernel() {
    __shared__ float4 Xs[E_];
    int tid = threadIdx.x;
    int i0 = blockIdx.x * 4;
    if (tid < E_) {
        float4 v;
        v.x = g_hemb[(size_t)(i0 + 0) * E_ + tid];
        v.y = g_hemb[(size_t)(i0 + 1) * E_ + tid];
        v.z = g_hemb[(size_t)(i0 + 2) * E_ + tid];
        v.w = g_hemb[(size_t)(i0 + 3) * E_ + tid];
        Xs[tid] = v;
    }
    __syncthreads();
    int n = tid;
    float bv = g_bd1_pad[n];
    float a0 = bv, a1 = bv, a2 = bv, a3 = bv;
#pragma unroll 5
    for (int kk = 0; kk < E_; kk++) {
        float w = g_Wd1T[kk * NP1 + n];
        float4 x = Xs[kk];
        a0 = fmaf(w, x.x, a0); a1 = fmaf(w, x.y, a1);
        a2 = fmaf(w, x.z, a2); a3 = fmaf(w, x.w, a3);
    }
    a0 = a0 >= 0.f ? a0 : 0.01f * a0;
    a1 = a1 >= 0.f ? a1 : 0.01f * a1;
    a2 = a2 >= 0.f ? a2 : 0.01f * a2;
    a3 = a3 >= 0.f ? a3 : 0.01f * a3;
    if (n < E_) {
        g_d1[(size_t)(i0 + 0) * E_ + n] = a0;
        g_d1[(size_t)(i0 + 1) * E_ + n] = a1;
        g_d1[(size_t)(i0 + 2) * E_ + n] = a2;
        g_d1[(size_t)(i0 + 3) * E_ + n] = a3;
    }
}

// ---------------- decoder stage 2: logits = d1 @ W_d2^T + b_d2 (masked) ----------------
#define AS4 9   // A_s row stride in float4 (36 floats)
__global__ void __launch_bounds__(256) logits_kernel(const float* __restrict__ bd2,
                                                     float* __restrict__ out) {
    __shared__ float4 A_s4[E_ * AS4];
    __shared__ int vld[32];
    float* A_s = (float*)A_s4;
    int tid = threadIdx.x;
    int i0 = blockIdx.x * 32;                 // row tile (i = kk*512 + b)
    int vt = blockIdx.y * 256;                // v tile

    if (tid < 32) {
        int i = i0 + tid;
        int kk = i >> 9, b = i & 511;
        vld[tid] = ((kk + 1) < g_len[b]) ? 1 : 0;
    }
    int any = __syncthreads_or(
        tid < 32 ? ((((i0 + tid) >> 9) + 1) < g_len[(i0 + tid) & 511]) : 0);

    int vq = vt + (tid & 63) * 4;
    int g2 = (tid >> 6) * 2;
    int rb = (tid >> 6) * 8;
    float4 acc[8];
#pragma unroll
    for (int r = 0; r < 8; r++) acc[r] = make_float4(0.f, 0.f, 0.f, 0.f);

    if (any) {
        for (int idx = tid; idx < 32 * E_; idx += 256) {
            int r = idx / E_, kk = idx - r * E_;
            A_s[kk * 36 + r] = g_d1[(size_t)(i0 + r) * E_ + kk];
        }
        __syncthreads();
        if (vq < V_) {
#pragma unroll 2
            for (int kk = 0; kk < E_; kk++) {
                float4 w = *(const float4*)&g_Wd2T[(size_t)kk * VP + vq];
                float4 xa = A_s4[kk * AS4 + g2];
                float4 xb = A_s4[kk * AS4 + g2 + 1];
                float ar[8] = {xa.x, xa.y, xa.z, xa.w, xb.x, xb.y, xb.z, xb.w};
#pragma unroll
                for (int r = 0; r < 8; r++) {
                    acc[r].x = fmaf(ar[r], w.x, acc[r].x);
                    acc[r].y = fmaf(ar[r], w.y, acc[r].y);
                    acc[r].z = fmaf(ar[r], w.z, acc[r].z);
                    acc[r].w = fmaf(ar[r], w.w, acc[r].w);
                }
            }
        }
    }

    if (vq < V_) {
        float4 bb = *(const float4*)&bd2[vq];
        const float4 zero = make_float4(0.f, 0.f, 0.f, 0.f);
#pragma unroll
        for (int r = 0; r < 8; r++) {
            int i = i0 + rb + r;
            int kk = i >> 9, b = i & 511;
            float4 o;
            if (vld[rb + r]) {
                o = make_float4(acc[r].x + bb.x, acc[r].y + bb.y,
                                acc[r].z + bb.z, acc[r].w + bb.w);
            } else {
                o = zero;
            }
            *(float4*)&out[((size_t)b * (T_ - 1) + kk) * V_ + vq] = o;
        }
    }
}

// ---------------- launch ----------------
extern "C" void kernel_launch(void* const* d_in, const int* in_sizes, int n_in,
                              void* d_out, int out_size) {
    (void)in_sizes; (void)n_in; (void)out_size;
    const float* codes   = (const float*)d_in[1];
    const int*   lengths = (const int*)d_in[2];
    const float* W_emb   = (const float*)d_in[3];
    const float* b_emb   = (const float*)d_in[4];
    const float* W1      = (const float*)d_in[5];
    const float* W2      = (const float*)d_in[6];
    const float* W3      = (const float*)d_in[7];
    const float* W_u     = (const float*)d_in[8];
    const float* b_u     = (const float*)d_in[9];
    const float* W_ih    = (const float*)d_in[10];
    const float* W_hh    = (const float*)d_in[11];
    const float* b_ih    = (const float*)d_in[12];
    const float* b_hh    = (const float*)d_in[13];
    const float* W_d1    = (const float*)d_in[14];
    const float* b_d1    = (const float*)d_in[15];
    const float* W_d2    = (const float*)d_in[16];
    const float* b_d2    = (const float*)d_in[17];
    float* out = (float*)d_out;

    static int smem_set = 0;
    if (!smem_set) {
        cudaFuncSetAttribute(seq_kernel, cudaFuncAttributeMaxDynamicSharedMemorySize,
                             SMEM_TOTAL_SEQ);
        smem_set = 1;
    }

    // Ordered so seq_kernel is my launch #4 (overall #6 for ncu -s 5 -c 1,
    // given the 2 harness-internal launches observed in R11).
    prep_wemb<<<(V_ * E_ + 255) / 256, 256>>>(W_emb);                          // 1
    prep_all<<<(4 * 330 * NP + 255) / 256, 256>>>(W1, W2, W3, W_u, b_u,
                                                  W_ih, W_hh, W_d1, b_d1);     // 2
    embed_kernel<<<B_ * T_, 256>>>(codes, b_emb);                              // 3
    seq_kernel<<<B_ / 4, 384, SMEM_TOTAL_SEQ>>>(b_ih, b_hh);                   // 4 <- profile
    prep_wd2<<<(E_ * VP + 255) / 256, 256>>>(W_d2);                            // 5
    prep_len<<<2, 256>>>(lengths);                                             // 6
    d1_kernel<<<((T_ - 1) * B_) / 4, NP1>>>();                                 // 7
    dim3 lgrid(((T_ - 1) * B_) / 32, (V_ + 255) / 256);
    logits_kernel<<<lgrid, 256>>>(b_d2, out);                                  // 8
}

// round 13
// speedup vs baseline: 1.5116x; 1.5116x over previous
#include <cuda_runtime.h>
#include <math.h>

#define B_  512
#define T_  24
#define V_  8000
#define E_  300
#define M_  30
#define H_  330
#define HP  352            // padded H (11 warps)
#define NSTEPS 8
#define DT_ 0.875f         // 7/8
#define VP  8192           // padded V for W_d2T
#define NP1 320            // padded N for d1 stage
#define KCH 33             // k-chunk for rotation (330 = 10*33)
#define NCH 10

// ---------------- device scratch (static, no allocation) ----------------
__device__ float g_WodeT[3 * HP * HP];   // [which][k][n] k<330 real, zero-padded
__device__ float g_WuT[HP * HP];         // [k<330][n<300]
__device__ float g_WihT[E_ * 96];        // [e<300][g<90]
__device__ float g_WhhT[M_ * 96];        // [m<30][g<90]
__device__ float g_Wd1T[E_ * NP1];       // [k<300][n<300]
__device__ float g_Wd2T[E_ * VP];        // [n<300][v<8000]
__device__ float g_WembT[V_ * E_];       // [v][e]
__device__ float g_bu_pad[HP];
__device__ float g_bd1_pad[NP1];
__device__ int   g_len[B_];
__device__ float g_gall[(size_t)B_ * T_ * E_];        // [b][t][e]
__device__ float g_hemb[(size_t)(T_ - 1) * B_ * E_];  // [kk][b][e]
__device__ float g_d1[(size_t)(T_ - 1) * B_ * E_];    // [kk][b][e]

// ---------------- lengths normalization (int32 vs int64 auto-detect) ----------------
__global__ void prep_len(const int* __restrict__ Lraw) {
    int b = blockIdx.x * blockDim.x + threadIdx.x;
    if (b >= B_) return;
    int is64 = (Lraw[1] == 0);
    g_len[b] = is64 ? Lraw[2 * b] : Lraw[b];
}

// ---------------- fused weight prep ----------------
__global__ void prep_all(const float* __restrict__ W1, const float* __restrict__ W2,
                         const float* __restrict__ W3, const float* __restrict__ Wu,
                         const float* __restrict__ bu,
                         const float* __restrict__ Wih, const float* __restrict__ Whh,
                         const float* __restrict__ Wd1, const float* __restrict__ bd1) {
    int i = blockIdx.x * blockDim.x + threadIdx.x;
    if (i < HP * HP) {
        int k = i / HP, n = i % HP;
        float v1 = 0.f, v2 = 0.f, v3 = 0.f, vu = 0.f;
        if (k < H_) {
            if (n < H_) {
                v1 = W1[n * H_ + k];
                v2 = W2[n * H_ + k];
                v3 = W3[n * H_ + k];
            }
            if (n < E_) vu = Wu[n * H_ + k];
        }
        g_WodeT[i] = v1;
        g_WodeT[HP * HP + i] = v2;
        g_WodeT[2 * HP * HP + i] = v3;
        g_WuT[i] = vu;
    }
    if (i < E_ * 96) {
        int e = i / 96, g = i % 96;
        g_WihT[i] = (g < 90) ? Wih[g * E_ + e] : 0.f;
    }
    if (i < M_ * 96) {
        int m = i / 96, g = i % 96;
        g_WhhT[i] = (g < 90) ? Whh[g * M_ + m] : 0.f;
    }
    if (i < E_ * NP1) {
        int k = i / NP1, n = i % NP1;
        g_Wd1T[i] = (n < E_) ? Wd1[n * E_ + k] : 0.f;
    }
    if (i < HP)  g_bu_pad[i]  = (i < E_) ? bu[i]  : 0.f;
    if (i < NP1) g_bd1_pad[i] = (i < E_) ? bd1[i] : 0.f;
}

__global__ void prep_wd2(const float* __restrict__ Wd2) {
    int i = blockIdx.x * blockDim.x + threadIdx.x;
    if (i >= E_ * VP) return;
    int n = i / VP, v = i % VP;
    g_Wd2T[i] = (v < V_) ? Wd2[v * E_ + n] : 0.f;
}

__global__ void prep_wemb(const float* __restrict__ Wemb) {
    int i = blockIdx.x * blockDim.x + threadIdx.x;
    if (i >= V_ * E_) return;
    int v = i / E_, e = i % E_;
    g_WembT[i] = Wemb[e * V_ + v];
}

// ---------------- sparse embedding (deterministic prefix-scan compaction) ----------------
__global__ void __launch_bounds__(256) embed_kernel(const float* __restrict__ codes,
                                                    const float* __restrict__ bemb) {
    __shared__ int idx[1024];
    __shared__ int cnts[256];
    __shared__ int total;
    int blk = blockIdx.x;               // blk = b*T_ + t
    int t = threadIdx.x;
    const float* crow = codes + (size_t)blk * V_;
    int base = t * 32;
    int c = 0;
#pragma unroll 4
    for (int j = 0; j < 32; j++) {
        int v = base + j;
        if (v < V_ && crow[v] != 0.f) c++;
    }
    cnts[t] = c;
    __syncthreads();
    for (int off = 1; off < 256; off <<= 1) {
        int val = cnts[t];
        int add = (t >= off) ? cnts[t - off] : 0;
        __syncthreads();
        cnts[t] = val + add;
        __syncthreads();
    }
    int p = cnts[t] - c;
    for (int j = 0; j < 32; j++) {
        int v = base + j;
        if (v < V_ && crow[v] != 0.f) {
            if (p < 1024) idx[p] = v;
            p++;
        }
    }
    if (t == 255) total = cnts[255];
    __syncthreads();
    int n = total > 1024 ? 1024 : total;
    for (int e = t; e < E_; e += 256) {
        float acc = bemb[e];
        for (int j = 0; j < n; j++) acc += g_WembT[idx[j] * E_ + e];
        g_gall[(size_t)blk * E_ + e] = acc;
    }
}

// ---------------- sequential ODE + GRU kernel ----------------
// k-rotated matmul stage: each CTA starts its k walk at chunk c0 so the 128
// CTAs spread their weight-line demand across ~10 distinct L2 lines instead
// of all hammering the same one (LTS same-line hotspot fix).
template <bool TANH, bool BIAS>
__device__ __forceinline__ void mm_stage(const float* __restrict__ WT,
                                         const float4* __restrict__ xs,
                                         float4* __restrict__ ys,
                                         const float* __restrict__ bias,
                                         int tid, int c0) {
    float a0 = 0.f, a1 = 0.f, a2 = 0.f, a3 = 0.f;
#pragma unroll 1
    for (int c = 0; c < NCH; c++) {
        int cc = c0 + c;
        if (cc >= NCH) cc -= NCH;
        const float* wp = WT + cc * (KCH * HP) + tid;
        const float4* xp = xs + cc * KCH;
#pragma unroll 11
        for (int k = 0; k < KCH; k++) {
            float w = wp[k * HP];
            float4 x = xp[k];
            a0 = fmaf(w, x.x, a0);
            a1 = fmaf(w, x.y, a1);
            a2 = fmaf(w, x.z, a2);
            a3 = fmaf(w, x.w, a3);
        }
    }
    if (BIAS) { float bv = bias[tid]; a0 += bv; a1 += bv; a2 += bv; a3 += bv; }
    if (TANH) { a0 = tanhf(a0); a1 = tanhf(a1); a2 = tanhf(a2); a3 = tanhf(a3); }
    ys[tid] = make_float4(a0, a1, a2, a3);
    __syncthreads();
}

__device__ __forceinline__ void ode_f(const float4* src, float4* bufA, float4* bufB,
                                      int tid, int c0) {
    mm_stage<true, false>(g_WodeT,               src,  bufA, nullptr, tid, c0);
    mm_stage<true, false>(g_WodeT + HP * HP,     bufA, bufB, nullptr, tid, c0);
    mm_stage<true, false>(g_WodeT + 2 * HP * HP, bufB, bufA, nullptr, tid, c0);
}

__device__ __forceinline__ float sigf(float x) { return 1.f / (1.f + expf(-x)); }

__global__ void __launch_bounds__(HP, 1) seq_kernel(const float* __restrict__ b_ih,
                                                    const float* __restrict__ b_hh) {
    __shared__ float4 Hs[HP], ACC[HP], Ys[HP], As[HP], Bs[HP];
    __shared__ float4 G1[96], G2[96];
    int tid = threadIdx.x;
    int b0 = blockIdx.x * 4;
    int c0 = blockIdx.x % NCH;          // per-CTA k-rotation phase

    // h0 = [zeros(M), g_all[:,0,:]]
    {
        float4 h = make_float4(0.f, 0.f, 0.f, 0.f);
        if (tid >= M_ && tid < H_) {
            int e = tid - M_;
            h.x = g_gall[((size_t)(b0 + 0) * T_ + 0) * E_ + e];
            h.y = g_gall[((size_t)(b0 + 1) * T_ + 0) * E_ + e];
            h.z = g_gall[((size_t)(b0 + 2) * T_ + 0) * E_ + e];
            h.w = g_gall[((size_t)(b0 + 3) * T_ + 0) * E_ + e];
        }
        Hs[tid] = h;
        __syncthreads();
    }

    for (int k = 1; k < T_; k++) {
        // ---- RK4 with N_STEPS substeps ----
        for (int s = 0; s < NSTEPS; s++) {
            ode_f(Hs, As, Bs, tid, c0);                          // k1 -> As
            {
                float4 a = As[tid], h = Hs[tid];
                ACC[tid] = a;
                Ys[tid] = make_float4(h.x + 0.5f * DT_ * a.x, h.y + 0.5f * DT_ * a.y,
                                      h.z + 0.5f * DT_ * a.z, h.w + 0.5f * DT_ * a.w);
                __syncthreads();
            }
            ode_f(Ys, As, Bs, tid, c0);                          // k2 -> As
            {
                float4 a = As[tid], h = Hs[tid], c = ACC[tid];
                ACC[tid] = make_float4(c.x + 2.f * a.x, c.y + 2.f * a.y,
                                       c.z + 2.f * a.z, c.w + 2.f * a.w);
                Ys[tid] = make_float4(h.x + 0.5f * DT_ * a.x, h.y + 0.5f * DT_ * a.y,
                                      h.z + 0.5f * DT_ * a.z, h.w + 0.5f * DT_ * a.w);
                __syncthreads();
            }
            ode_f(Ys, As, Bs, tid, c0);                          // k3 -> As
            {
                float4 a = As[tid], h = Hs[tid], c = ACC[tid];
                ACC[tid] = make_float4(c.x + 2.f * a.x, c.y + 2.f * a.y,
                                       c.z + 2.f * a.z, c.w + 2.f * a.w);
                Ys[tid] = make_float4(h.x + DT_ * a.x, h.y + DT_ * a.y,
                                      h.z + DT_ * a.z, h.w + DT_ * a.w);
                __syncthreads();
            }
            ode_f(Ys, As, Bs, tid, c0);                          // k4 -> As
            {
                const float c6 = DT_ / 6.f;
                float4 a = As[tid], h = Hs[tid], c = ACC[tid];
                Hs[tid] = make_float4(h.x + c6 * (c.x + a.x), h.y + c6 * (c.y + a.y),
                                      h.z + c6 * (c.z + a.z), h.w + c6 * (c.w + a.w));
                __syncthreads();
            }
        }

        // ---- dump h_emb for the decoupled decoder; build cin = [h_mem, g_k] ----
        if (tid < E_) {
            float4 v = Hs[M_ + tid];
            size_t base = ((size_t)(k - 1) * B_ + b0) * E_ + tid;
            g_hemb[base]          = v.x;
            g_hemb[base + E_]     = v.y;
            g_hemb[base + 2 * E_] = v.z;
            g_hemb[base + 3 * E_] = v.w;
        }
        {
            float4 c = make_float4(0.f, 0.f, 0.f, 0.f);
            if (tid < M_) c = Hs[tid];
            else if (tid < H_) {
                int e = tid - M_;
                c.x = g_gall[((size_t)(b0 + 0) * T_ + k) * E_ + e];
                c.y = g_gall[((size_t)(b0 + 1) * T_ + k) * E_ + e];
                c.z = g_gall[((size_t)(b0 + 2) * T_ + k) * E_ + e];
                c.w = g_gall[((size_t)(b0 + 3) * T_ + k) * E_ + e];
            }
            Ys[tid] = c;
            __syncthreads();
        }

        // ---- x = cin @ W_u^T + b_u  -> As ----
        mm_stage<false, true>(g_WuT, Ys, As, g_bu_pad, tid, c0);

        // ---- GRU gates ----
        if (tid < 96) {
            int g = tid;
            float bb = (g < 90) ? b_ih[g] : 0.f;
            float4 a = make_float4(bb, bb, bb, bb);
#pragma unroll 4
            for (int e = 0; e < E_; e++) {
                float w = g_WihT[e * 96 + g];
                float4 x = As[e];
                a.x = fmaf(w, x.x, a.x); a.y = fmaf(w, x.y, a.y);
                a.z = fmaf(w, x.z, a.z); a.w = fmaf(w, x.w, a.w);
            }
            G1[g] = a;
        } else if (tid < 192) {
            int g = tid - 96;
            float bb = (g < 90) ? b_hh[g] : 0.f;
            float4 a = make_float4(bb, bb, bb, bb);
#pragma unroll
            for (int m = 0; m < M_; m++) {
                float w = g_WhhT[m * 96 + g];
                float4 x = Hs[m];
                a.x = fmaf(w, x.x, a.x); a.y = fmaf(w, x.y, a.y);
                a.z = fmaf(w, x.z, a.z); a.w = fmaf(w, x.w, a.w);
            }
            G2[g] = a;
        }
        __syncthreads();

        if (tid < M_) {
            int m = tid;
            float4 xr = G1[m],          hr = G2[m];
            float4 xz = G1[M_ + m],     hz = G2[M_ + m];
            float4 xn = G1[2 * M_ + m], hn = G2[2 * M_ + m];
            float4 ho = Hs[m];
            float4 hv;
            { float r = sigf(xr.x + hr.x), z = sigf(xz.x + hz.x);
              float t = tanhf(xn.x + r * hn.x); hv.x = (1.f - z) * t + z * ho.x; }
            { float r = sigf(xr.y + hr.y), z = sigf(xz.y + hz.y);
              float t = tanhf(xn.y + r * hn.y); hv.y = (1.f - z) * t + z * ho.y; }
            { float r = sigf(xr.z + hr.z), z = sigf(xz.z + hz.z);
              float t = tanhf(xn.z + r * hn.z); hv.z = (1.f - z) * t + z * ho.z; }
            { float r = sigf(xr.w + hr.w), z = sigf(xz.w + hz.w);
              float t = tanhf(xn.w + r * hn.w); hv.w = (1.f - z) * t + z * ho.w; }
            Hs[m] = hv;
        }
        __syncthreads();
    }
}

// ---------------- decoder stage 1: d1 = leaky_relu(hemb @ W_d1^T + b_d1) ----------------
__global__ void __launch_bounds__(NP1) d1_kernel() {
    __shared__ float4 Xs[E_];
    int tid = threadIdx.x;
    int i0 = blockIdx.x * 4;
    if (tid < E_) {
        float4 v;
        v.x = g_hemb[(size_t)(i0 + 0) * E_ + tid];
        v.y = g_hemb[(size_t)(i0 + 1) * E_ + tid];
        v.z = g_hemb[(size_t)(i0 + 2) * E_ + tid];
        v.w = g_hemb[(size_t)(i0 + 3) * E_ + tid];
        Xs[tid] = v;
    }
    __syncthreads();
    int n = tid;
    float bv = g_bd1_pad[n];
    float a0 = bv, a1 = bv, a2 = bv, a3 = bv;
#pragma unroll 5
    for (int kk = 0; kk < E_; kk++) {
        float w = g_Wd1T[kk * NP1 + n];
        float4 x = Xs[kk];
        a0 = fmaf(w, x.x, a0); a1 = fmaf(w, x.y, a1);
        a2 = fmaf(w, x.z, a2); a3 = fmaf(w, x.w, a3);
    }
    a0 = a0 >= 0.f ? a0 : 0.01f * a0;
    a1 = a1 >= 0.f ? a1 : 0.01f * a1;
    a2 = a2 >= 0.f ? a2 : 0.01f * a2;
    a3 = a3 >= 0.f ? a3 : 0.01f * a3;
    if (n < E_) {
        g_d1[(size_t)(i0 + 0) * E_ + n] = a0;
        g_d1[(size_t)(i0 + 1) * E_ + n] = a1;
        g_d1[(size_t)(i0 + 2) * E_ + n] = a2;
        g_d1[(size_t)(i0 + 3) * E_ + n] = a3;
    }
}

// ---------------- decoder stage 2: logits = d1 @ W_d2^T + b_d2 (masked) ----------------
#define AS4 9   // A_s row stride in float4 (36 floats)
__global__ void __launch_bounds__(256) logits_kernel(const float* __restrict__ bd2,
                                                     float* __restrict__ out) {
    __shared__ float4 A_s4[E_ * AS4];
    __shared__ int vld[32];
    float* A_s = (float*)A_s4;
    int tid = threadIdx.x;
    int i0 = blockIdx.x * 32;                 // row tile (i = kk*512 + b)
    int vt = blockIdx.y * 256;                // v tile

    if (tid < 32) {
        int i = i0 + tid;
        int kk = i >> 9, b = i & 511;
        vld[tid] = ((kk + 1) < g_len[b]) ? 1 : 0;
    }
    int any = __syncthreads_or(
        tid < 32 ? ((((i0 + tid) >> 9) + 1) < g_len[(i0 + tid) & 511]) : 0);

    int vq = vt + (tid & 63) * 4;
    int g2 = (tid >> 6) * 2;
    int rb = (tid >> 6) * 8;
    float4 acc[8];
#pragma unroll
    for (int r = 0; r < 8; r++) acc[r] = make_float4(0.f, 0.f, 0.f, 0.f);

    if (any) {
        for (int idx = tid; idx < 32 * E_; idx += 256) {
            int r = idx / E_, kk = idx - r * E_;
            A_s[kk * 36 + r] = g_d1[(size_t)(i0 + r) * E_ + kk];
        }
        __syncthreads();
        if (vq < V_) {
#pragma unroll 2
            for (int kk = 0; kk < E_; kk++) {
                float4 w = *(const float4*)&g_Wd2T[(size_t)kk * VP + vq];
                float4 xa = A_s4[kk * AS4 + g2];
                float4 xb = A_s4[kk * AS4 + g2 + 1];
                float ar[8] = {xa.x, xa.y, xa.z, xa.w, xb.x, xb.y, xb.z, xb.w};
#pragma unroll
                for (int r = 0; r < 8; r++) {
                    acc[r].x = fmaf(ar[r], w.x, acc[r].x);
                    acc[r].y = fmaf(ar[r], w.y, acc[r].y);
                    acc[r].z = fmaf(ar[r], w.z, acc[r].z);
                    acc[r].w = fmaf(ar[r], w.w, acc[r].w);
                }
            }
        }
    }

    if (vq < V_) {
        float4 bb = *(const float4*)&bd2[vq];
        const float4 zero = make_float4(0.f, 0.f, 0.f, 0.f);
#pragma unroll
        for (int r = 0; r < 8; r++) {
            int i = i0 + rb + r;
            int kk = i >> 9, b = i & 511;
            float4 o;
            if (vld[rb + r]) {
                o = make_float4(acc[r].x + bb.x, acc[r].y + bb.y,
                                acc[r].z + bb.z, acc[r].w + bb.w);
            } else {
                o = zero;
            }
            *(float4*)&out[((size_t)b * (T_ - 1) + kk) * V_ + vq] = o;
        }
    }
}

// ---------------- launch ----------------
extern "C" void kernel_launch(void* const* d_in, const int* in_sizes, int n_in,
                              void* d_out, int out_size) {
    (void)in_sizes; (void)n_in; (void)out_size;
    const float* codes   = (const float*)d_in[1];
    const int*   lengths = (const int*)d_in[2];
    const float* W_emb   = (const float*)d_in[3];
    const float* b_emb   = (const float*)d_in[4];
    const float* W1      = (const float*)d_in[5];
    const float* W2      = (const float*)d_in[6];
    const float* W3      = (const float*)d_in[7];
    const float* W_u     = (const float*)d_in[8];
    const float* b_u     = (const float*)d_in[9];
    const float* W_ih    = (const float*)d_in[10];
    const float* W_hh    = (const float*)d_in[11];
    const float* b_ih    = (const float*)d_in[12];
    const float* b_hh    = (const float*)d_in[13];
    const float* W_d1    = (const float*)d_in[14];
    const float* b_d1    = (const float*)d_in[15];
    const float* W_d2    = (const float*)d_in[16];
    const float* b_d2    = (const float*)d_in[17];
    float* out = (float*)d_out;

    // seq_kernel is my launch #4 = overall #6 for ncu -s 5 -c 1 (2 harness
    // pre-launches confirmed by R12 capture).
    prep_wemb<<<(V_ * E_ + 255) / 256, 256>>>(W_emb);                          // 1
    prep_all<<<(HP * HP + 255) / 256, 256>>>(W1, W2, W3, W_u, b_u,
                                             W_ih, W_hh, W_d1, b_d1);          // 2
    embed_kernel<<<B_ * T_, 256>>>(codes, b_emb);                              // 3
    seq_kernel<<<B_ / 4, HP>>>(b_ih, b_hh);                                    // 4 <- profiled
    prep_wd2<<<(E_ * VP + 255) / 256, 256>>>(W_d2);                            // 5
    prep_len<<<2, 256>>>(lengths);                                             // 6
    d1_kernel<<<((T_ - 1) * B_) / 4, NP1>>>();                                 // 7
    dim3 lgrid(((T_ - 1) * B_) / 32, (V_ + 255) / 256);
    logits_kernel<<<lgrid, 256>>>(b_d2, out);                                  // 8
}

// round 14
// speedup vs baseline: 1.9958x; 1.3204x over previous
#include <cuda_runtime.h>
#include <math.h>

#define B_  512
#define T_  24
#define V_  8000
#define E_  300
#define M_  30
#define H_  330
#define HP  352            // padded H (11 warps)
#define NSTEPS 8
#define DT_ 0.875f         // 7/8
#define VP  8192           // padded V for W_d2T
#define NP1 320            // padded N for d1 stage
#define GK  22             // k-group size (pipeline granule)
#define NG  15             // 330 = 15 * 22

// ---------------- device scratch (static, no allocation) ----------------
__device__ float g_WodeT[3 * HP * HP];   // [which][k][n] k<330 real, zero-padded
__device__ float g_WuT[HP * HP];         // [k<330][n<300]
__device__ float g_WihT[E_ * 96];        // [e<300][g<90]
__device__ float g_WhhT[M_ * 96];        // [m<30][g<90]
__device__ float g_Wd1T[E_ * NP1];       // [k<300][n<300]
__device__ float g_Wd2T[E_ * VP];        // [n<300][v<8000]
__device__ float g_WembT[V_ * E_];       // [v][e]
__device__ float g_bu_pad[HP];
__device__ float g_bd1_pad[NP1];
__device__ int   g_len[B_];
__device__ float g_gall[(size_t)B_ * T_ * E_];        // [b][t][e]
__device__ float g_hemb[(size_t)(T_ - 1) * B_ * E_];  // [kk][b][e]
__device__ float g_d1[(size_t)(T_ - 1) * B_ * E_];    // [kk][b][e]

// ---------------- lengths normalization (int32 vs int64 auto-detect) ----------------
__global__ void prep_len(const int* __restrict__ Lraw) {
    int b = blockIdx.x * blockDim.x + threadIdx.x;
    if (b >= B_) return;
    int is64 = (Lraw[1] == 0);
    g_len[b] = is64 ? Lraw[2 * b] : Lraw[b];
}

// ---------------- fused weight prep ----------------
__global__ void prep_all(const float* __restrict__ W1, const float* __restrict__ W2,
                         const float* __restrict__ W3, const float* __restrict__ Wu,
                         const float* __restrict__ bu,
                         const float* __restrict__ Wih, const float* __restrict__ Whh,
                         const float* __restrict__ Wd1, const float* __restrict__ bd1) {
    int i = blockIdx.x * blockDim.x + threadIdx.x;
    if (i < HP * HP) {
        int k = i / HP, n = i % HP;
        float v1 = 0.f, v2 = 0.f, v3 = 0.f, vu = 0.f;
        if (k < H_) {
            if (n < H_) {
                v1 = W1[n * H_ + k];
                v2 = W2[n * H_ + k];
                v3 = W3[n * H_ + k];
            }
            if (n < E_) vu = Wu[n * H_ + k];
        }
        g_WodeT[i] = v1;
        g_WodeT[HP * HP + i] = v2;
        g_WodeT[2 * HP * HP + i] = v3;
        g_WuT[i] = vu;
    }
    if (i < E_ * 96) {
        int e = i / 96, g = i % 96;
        g_WihT[i] = (g < 90) ? Wih[g * E_ + e] : 0.f;
    }
    if (i < M_ * 96) {
        int m = i / 96, g = i % 96;
        g_WhhT[i] = (g < 90) ? Whh[g * M_ + m] : 0.f;
    }
    if (i < E_ * NP1) {
        int k = i / NP1, n = i % NP1;
        g_Wd1T[i] = (n < E_) ? Wd1[n * E_ + k] : 0.f;
    }
    if (i < HP)  g_bu_pad[i]  = (i < E_) ? bu[i]  : 0.f;
    if (i < NP1) g_bd1_pad[i] = (i < E_) ? bd1[i] : 0.f;
}

__global__ void prep_wd2(const float* __restrict__ Wd2) {
    int i = blockIdx.x * blockDim.x + threadIdx.x;
    if (i >= E_ * VP) return;
    int n = i / VP, v = i % VP;
    g_Wd2T[i] = (v < V_) ? Wd2[v * E_ + n] : 0.f;
}

__global__ void prep_wemb(const float* __restrict__ Wemb) {
    int i = blockIdx.x * blockDim.x + threadIdx.x;
    if (i >= V_ * E_) return;
    int v = i / E_, e = i % E_;
    g_WembT[i] = Wemb[e * V_ + v];
}

// ---------------- sparse embedding (deterministic prefix-scan compaction) ----------------
__global__ void __launch_bounds__(256) embed_kernel(const float* __restrict__ codes,
                                                    const float* __restrict__ bemb) {
    __shared__ int idx[1024];
    __shared__ int cnts[256];
    __shared__ int total;
    int blk = blockIdx.x;               // blk = b*T_ + t
    int t = threadIdx.x;
    const float* crow = codes + (size_t)blk * V_;
    int base = t * 32;
    int c = 0;
#pragma unroll 4
    for (int j = 0; j < 32; j++) {
        int v = base + j;
        if (v < V_ && crow[v] != 0.f) c++;
    }
    cnts[t] = c;
    __syncthreads();
    for (int off = 1; off < 256; off <<= 1) {
        int val = cnts[t];
        int add = (t >= off) ? cnts[t - off] : 0;
        __syncthreads();
        cnts[t] = val + add;
        __syncthreads();
    }
    int p = cnts[t] - c;
    for (int j = 0; j < 32; j++) {
        int v = base + j;
        if (v < V_ && crow[v] != 0.f) {
            if (p < 1024) idx[p] = v;
            p++;
        }
    }
    if (t == 255) total = cnts[255];
    __syncthreads();
    int n = total > 1024 ? 1024 : total;
    for (int e = t; e < E_; e += 256) {
        float acc = bemb[e];
        for (int j = 0; j < n; j++) acc += g_WembT[idx[j] * E_ + e];
        g_gall[(size_t)blk * E_ + e] = acc;
    }
}

// ---------------- sequential ODE + GRU kernel ----------------
// Software-pipelined matmul stage: 15 groups of 22 k-rows, ping-pong register
// prefetch (weights for group g+1 load while group g's FFMAs run) so L2
// latency is fully hidden. Per-warp rotation phase g0 spreads the 128 CTAs'
// weight-line demand across ~165 line-phases (LTS same-line hotspot fix).
template <bool TANH, bool BIAS>
__device__ __forceinline__ void mm_stage(const float* __restrict__ WT,
                                         const float4* __restrict__ xs,
                                         float4* __restrict__ ys,
                                         const float* __restrict__ bias,
                                         int tid, int g0) {
    float a0 = 0.f, a1 = 0.f, a2 = 0.f, a3 = 0.f;
    const float* wp = WT + tid;
    float wA[GK], wB[GK];
    int g = g0;
#pragma unroll
    for (int j = 0; j < GK; j++) wA[j] = wp[(g * GK + j) * HP];
#pragma unroll 1
    for (int it = 0; it < NG - 1; it += 2) {
        int g1 = g + 1; if (g1 >= NG) g1 -= NG;
#pragma unroll
        for (int j = 0; j < GK; j++) wB[j] = wp[(g1 * GK + j) * HP];
        {
            const float4* xp = xs + g * GK;
#pragma unroll
            for (int j = 0; j < GK; j++) {
                float4 x = xp[j];
                a0 = fmaf(wA[j], x.x, a0); a1 = fmaf(wA[j], x.y, a1);
                a2 = fmaf(wA[j], x.z, a2); a3 = fmaf(wA[j], x.w, a3);
            }
        }
        int g2 = g1 + 1; if (g2 >= NG) g2 -= NG;
#pragma unroll
        for (int j = 0; j < GK; j++) wA[j] = wp[(g2 * GK + j) * HP];
        {
            const float4* xp = xs + g1 * GK;
#pragma unroll
            for (int j = 0; j < GK; j++) {
                float4 x = xp[j];
                a0 = fmaf(wB[j], x.x, a0); a1 = fmaf(wB[j], x.y, a1);
                a2 = fmaf(wB[j], x.z, a2); a3 = fmaf(wB[j], x.w, a3);
            }
        }
        g = g2;
    }
    // 7 pairs computed groups g0..g0+13 (mod NG); wA holds group g0+14.
    {
        const float4* xp = xs + g * GK;
#pragma unroll
        for (int j = 0; j < GK; j++) {
            float4 x = xp[j];
            a0 = fmaf(wA[j], x.x, a0); a1 = fmaf(wA[j], x.y, a1);
            a2 = fmaf(wA[j], x.z, a2); a3 = fmaf(wA[j], x.w, a3);
        }
    }
    if (BIAS) { float bv = bias[tid]; a0 += bv; a1 += bv; a2 += bv; a3 += bv; }
    if (TANH) { a0 = tanhf(a0); a1 = tanhf(a1); a2 = tanhf(a2); a3 = tanhf(a3); }
    ys[tid] = make_float4(a0, a1, a2, a3);
    __syncthreads();
}

__device__ __forceinline__ void ode_f(const float4* src, float4* bufA, float4* bufB,
                                      int tid, int g0) {
    mm_stage<true, false>(g_WodeT,               src,  bufA, nullptr, tid, g0);
    mm_stage<true, false>(g_WodeT + HP * HP,     bufA, bufB, nullptr, tid, g0);
    mm_stage<true, false>(g_WodeT + 2 * HP * HP, bufB, bufA, nullptr, tid, g0);
}

__device__ __forceinline__ float sigf(float x) { return 1.f / (1.f + expf(-x)); }

__global__ void __launch_bounds__(HP, 1) seq_kernel(const float* __restrict__ b_ih,
                                                    const float* __restrict__ b_hh) {
    __shared__ float4 Hs[HP], ACC[HP], Ys[HP], As[HP], Bs[HP];
    __shared__ float4 G1[96], G2[96];
    int tid = threadIdx.x;
    int b0 = blockIdx.x * 4;
    int g0 = (blockIdx.x * 11 + (tid >> 5)) % NG;     // per-warp rotation phase

    // h0 = [zeros(M), g_all[:,0,:]]
    {
        float4 h = make_float4(0.f, 0.f, 0.f, 0.f);
        if (tid >= M_ && tid < H_) {
            int e = tid - M_;
            h.x = g_gall[((size_t)(b0 + 0) * T_ + 0) * E_ + e];
            h.y = g_gall[((size_t)(b0 + 1) * T_ + 0) * E_ + e];
            h.z = g_gall[((size_t)(b0 + 2) * T_ + 0) * E_ + e];
            h.w = g_gall[((size_t)(b0 + 3) * T_ + 0) * E_ + e];
        }
        Hs[tid] = h;
        __syncthreads();
    }

    for (int k = 1; k < T_; k++) {
        // ---- RK4 with N_STEPS substeps ----
        for (int s = 0; s < NSTEPS; s++) {
            ode_f(Hs, As, Bs, tid, g0);                          // k1 -> As
            {
                float4 a = As[tid], h = Hs[tid];
                ACC[tid] = a;
                Ys[tid] = make_float4(h.x + 0.5f * DT_ * a.x, h.y + 0.5f * DT_ * a.y,
                                      h.z + 0.5f * DT_ * a.z, h.w + 0.5f * DT_ * a.w);
                __syncthreads();
            }
            ode_f(Ys, As, Bs, tid, g0);                          // k2 -> As
            {
                float4 a = As[tid], h = Hs[tid], c = ACC[tid];
                ACC[tid] = make_float4(c.x + 2.f * a.x, c.y + 2.f * a.y,
                                       c.z + 2.f * a.z, c.w + 2.f * a.w);
                Ys[tid] = make_float4(h.x + 0.5f * DT_ * a.x, h.y + 0.5f * DT_ * a.y,
                                      h.z + 0.5f * DT_ * a.z, h.w + 0.5f * DT_ * a.w);
                __syncthreads();
            }
            ode_f(Ys, As, Bs, tid, g0);                          // k3 -> As
            {
                float4 a = As[tid], h = Hs[tid], c = ACC[tid];
                ACC[tid] = make_float4(c.x + 2.f * a.x, c.y + 2.f * a.y,
                                       c.z + 2.f * a.z, c.w + 2.f * a.w);
                Ys[tid] = make_float4(h.x + DT_ * a.x, h.y + DT_ * a.y,
                                      h.z + DT_ * a.z, h.w + DT_ * a.w);
                __syncthreads();
            }
            ode_f(Ys, As, Bs, tid, g0);                          // k4 -> As
            {
                const float c6 = DT_ / 6.f;
                float4 a = As[tid], h = Hs[tid], c = ACC[tid];
                Hs[tid] = make_float4(h.x + c6 * (c.x + a.x), h.y + c6 * (c.y + a.y),
                                      h.z + c6 * (c.z + a.z), h.w + c6 * (c.w + a.w));
                __syncthreads();
            }
        }

        // ---- dump h_emb for the decoupled decoder; build cin = [h_mem, g_k] ----
        if (tid < E_) {
            float4 v = Hs[M_ + tid];
            size_t base = ((size_t)(k - 1) * B_ + b0) * E_ + tid;
            g_hemb[base]          = v.x;
            g_hemb[base + E_]     = v.y;
            g_hemb[base + 2 * E_] = v.z;
            g_hemb[base + 3 * E_] = v.w;
        }
        {
            float4 c = make_float4(0.f, 0.f, 0.f, 0.f);
            if (tid < M_) c = Hs[tid];
            else if (tid < H_) {
                int e = tid - M_;
                c.x = g_gall[((size_t)(b0 + 0) * T_ + k) * E_ + e];
                c.y = g_gall[((size_t)(b0 + 1) * T_ + k) * E_ + e];
                c.z = g_gall[((size_t)(b0 + 2) * T_ + k) * E_ + e];
                c.w = g_gall[((size_t)(b0 + 3) * T_ + k) * E_ + e];
            }
            Ys[tid] = c;
            __syncthreads();
        }

        // ---- x = cin @ W_u^T + b_u  -> As ----
        mm_stage<false, true>(g_WuT, Ys, As, g_bu_pad, tid, g0);

        // ---- GRU gates ----
        if (tid < 96) {
            int g = tid;
            float bb = (g < 90) ? b_ih[g] : 0.f;
            float4 a = make_float4(bb, bb, bb, bb);
#pragma unroll 4
            for (int e = 0; e < E_; e++) {
                float w = g_WihT[e * 96 + g];
                float4 x = As[e];
                a.x = fmaf(w, x.x, a.x); a.y = fmaf(w, x.y, a.y);
                a.z = fmaf(w, x.z, a.z); a.w = fmaf(w, x.w, a.w);
            }
            G1[g] = a;
        } else if (tid < 192) {
            int g = tid - 96;
            float bb = (g < 90) ? b_hh[g] : 0.f;
            float4 a = make_float4(bb, bb, bb, bb);
#pragma unroll
            for (int m = 0; m < M_; m++) {
                float w = g_WhhT[m * 96 + g];
                float4 x = Hs[m];
                a.x = fmaf(w, x.x, a.x); a.y = fmaf(w, x.y, a.y);
                a.z = fmaf(w, x.z, a.z); a.w = fmaf(w, x.w, a.w);
            }
            G2[g] = a;
        }
        __syncthreads();

        if (tid < M_) {
            int m = tid;
            float4 xr = G1[m],          hr = G2[m];
            float4 xz = G1[M_ + m],     hz = G2[M_ + m];
            float4 xn = G1[2 * M_ + m], hn = G2[2 * M_ + m];
            float4 ho = Hs[m];
            float4 hv;
            { float r = sigf(xr.x + hr.x), z = sigf(xz.x + hz.x);
              float t = tanhf(xn.x + r * hn.x); hv.x = (1.f - z) * t + z * ho.x; }
            { float r = sigf(xr.y + hr.y), z = sigf(xz.y + hz.y);
              float t = tanhf(xn.y + r * hn.y); hv.y = (1.f - z) * t + z * ho.y; }
            { float r = sigf(xr.z + hr.z), z = sigf(xz.z + hz.z);
              float t = tanhf(xn.z + r * hn.z); hv.z = (1.f - z) * t + z * ho.z; }
            { float r = sigf(xr.w + hr.w), z = sigf(xz.w + hz.w);
              float t = tanhf(xn.w + r * hn.w); hv.w = (1.f - z) * t + z * ho.w; }
            Hs[m] = hv;
        }
        __syncthreads();
    }
}

// ---------------- decoder stage 1: d1 = leaky_relu(hemb @ W_d1^T + b_d1) ----------------
__global__ void __launch_bounds__(NP1) d1_kernel() {
    __shared__ float4 Xs[E_];
    int tid = threadIdx.x;
    int i0 = blockIdx.x * 4;
    if (tid < E_) {
        float4 v;
        v.x = g_hemb[(size_t)(i0 + 0) * E_ + tid];
        v.y = g_hemb[(size_t)(i0 + 1) * E_ + tid];
        v.z = g_hemb[(size_t)(i0 + 2) * E_ + tid];
        v.w = g_hemb[(size_t)(i0 + 3) * E_ + tid];
        Xs[tid] = v;
    }
    __syncthreads();
    int n = tid;
    float bv = g_bd1_pad[n];
    float a0 = bv, a1 = bv, a2 = bv, a3 = bv;
#pragma unroll 5
    for (int kk = 0; kk < E_; kk++) {
        float w = g_Wd1T[kk * NP1 + n];
        float4 x = Xs[kk];
        a0 = fmaf(w, x.x, a0); a1 = fmaf(w, x.y, a1);
        a2 = fmaf(w, x.z, a2); a3 = fmaf(w, x.w, a3);
    }
    a0 = a0 >= 0.f ? a0 : 0.01f * a0;
    a1 = a1 >= 0.f ? a1 : 0.01f * a1;
    a2 = a2 >= 0.f ? a2 : 0.01f * a2;
    a3 = a3 >= 0.f ? a3 : 0.01f * a3;
    if (n < E_) {
        g_d1[(size_t)(i0 + 0) * E_ + n] = a0;
        g_d1[(size_t)(i0 + 1) * E_ + n] = a1;
        g_d1[(size_t)(i0 + 2) * E_ + n] = a2;
        g_d1[(size_t)(i0 + 3) * E_ + n] = a3;
    }
}

// ---------------- decoder stage 2: logits = d1 @ W_d2^T + b_d2 (masked) ----------------
#define AS4 9   // A_s row stride in float4 (36 floats)
__global__ void __launch_bounds__(256) logits_kernel(const float* __restrict__ bd2,
                                                     float* __restrict__ out) {
    __shared__ float4 A_s4[E_ * AS4];
    __shared__ int vld[32];
    float* A_s = (float*)A_s4;
    int tid = threadIdx.x;
    int i0 = blockIdx.x * 32;                 // row tile (i = kk*512 + b)
    int vt = blockIdx.y * 256;                // v tile

    if (tid < 32) {
        int i = i0 + tid;
        int kk = i >> 9, b = i & 511;
        vld[tid] = ((kk + 1) < g_len[b]) ? 1 : 0;
    }
    int any = __syncthreads_or(
        tid < 32 ? ((((i0 + tid) >> 9) + 1) < g_len[(i0 + tid) & 511]) : 0);

    int vq = vt + (tid & 63) * 4;
    int g2 = (tid >> 6) * 2;
    int rb = (tid >> 6) * 8;
    float4 acc[8];
#pragma unroll
    for (int r = 0; r < 8; r++) acc[r] = make_float4(0.f, 0.f, 0.f, 0.f);

    if (any) {
        for (int idx = tid; idx < 32 * E_; idx += 256) {
            int r = idx / E_, kk = idx - r * E_;
            A_s[kk * 36 + r] = g_d1[(size_t)(i0 + r) * E_ + kk];
        }
        __syncthreads();
        if (vq < V_) {
#pragma unroll 2
            for (int kk = 0; kk < E_; kk++) {
                float4 w = *(const float4*)&g_Wd2T[(size_t)kk * VP + vq];
                float4 xa = A_s4[kk * AS4 + g2];
                float4 xb = A_s4[kk * AS4 + g2 + 1];
                float ar[8] = {xa.x, xa.y, xa.z, xa.w, xb.x, xb.y, xb.z, xb.w};
#pragma unroll
                for (int r = 0; r < 8; r++) {
                    acc[r].x = fmaf(ar[r], w.x, acc[r].x);
                    acc[r].y = fmaf(ar[r], w.y, acc[r].y);
                    acc[r].z = fmaf(ar[r], w.z, acc[r].z);
                    acc[r].w = fmaf(ar[r], w.w, acc[r].w);
                }
            }
        }
    }

    if (vq < V_) {
        float4 bb = *(const float4*)&bd2[vq];
        const float4 zero = make_float4(0.f, 0.f, 0.f, 0.f);
#pragma unroll
        for (int r = 0; r < 8; r++) {
            int i = i0 + rb + r;
            int kk = i >> 9, b = i & 511;
            float4 o;
            if (vld[rb + r]) {
                o = make_float4(acc[r].x + bb.x, acc[r].y + bb.y,
                                acc[r].z + bb.z, acc[r].w + bb.w);
            } else {
                o = zero;
            }
            *(float4*)&out[((size_t)b * (T_ - 1) + kk) * V_ + vq] = o;
        }
    }
}

// ---------------- launch ----------------
extern "C" void kernel_launch(void* const* d_in, const int* in_sizes, int n_in,
                              void* d_out, int out_size) {
    (void)in_sizes; (void)n_in; (void)out_size;
    const float* codes   = (const float*)d_in[1];
    const int*   lengths = (const int*)d_in[2];
    const float* W_emb   = (const float*)d_in[3];
    const float* b_emb   = (const float*)d_in[4];
    const float* W1      = (const float*)d_in[5];
    const float* W2      = (const float*)d_in[6];
    const float* W3      = (const float*)d_in[7];
    const float* W_u     = (const float*)d_in[8];
    const float* b_u     = (const float*)d_in[9];
    const float* W_ih    = (const float*)d_in[10];
    const float* W_hh    = (const float*)d_in[11];
    const float* b_ih    = (const float*)d_in[12];
    const float* b_hh    = (const float*)d_in[13];
    const float* W_d1    = (const float*)d_in[14];
    const float* b_d1    = (const float*)d_in[15];
    const float* W_d2    = (const float*)d_in[16];
    const float* b_d2    = (const float*)d_in[17];
    float* out = (float*)d_out;

    // seq_kernel is my launch #4 = overall #6 for ncu -s 5 -c 1.
    prep_wemb<<<(V_ * E_ + 255) / 256, 256>>>(W_emb);                          // 1
    prep_all<<<(HP * HP + 255) / 256, 256>>>(W1, W2, W3, W_u, b_u,
                                             W_ih, W_hh, W_d1, b_d1);          // 2
    embed_kernel<<<B_ * T_, 256>>>(codes, b_emb);                              // 3
    seq_kernel<<<B_ / 4, HP>>>(b_ih, b_hh);                                    // 4 <- profiled
    prep_wd2<<<(E_ * VP + 255) / 256, 256>>>(W_d2);                            // 5
    prep_len<<<2, 256>>>(lengths);                                             // 6
    d1_kernel<<<((T_ - 1) * B_) / 4, NP1>>>();                                 // 7
    dim3 lgrid(((T_ - 1) * B_) / 32, (V_ + 255) / 256);
    logits_kernel<<<lgrid, 256>>>(b_d2, out);                                  // 8
}

// round 15
// speedup vs baseline: 2.0018x; 1.0030x over previous
#include <cuda_runtime.h>
#include <math.h>

#define B_  512
#define T_  24
#define V_  8000
#define E_  300
#define M_  30
#define H_  330
#define HP  352            // padded n-columns (11 warps)
#define NSTEPS 8
#define DT_ 0.875f         // 7/8
#define VP  8192           // padded V for W_d2T
#define NP1 320            // padded N for d1 stage
#define NQ  84             // k-quads per matrix (K padded to 336; quad 83 all-zero, skipped)
#define CQ  11             // cached quads per ODE matrix (smem prefix)
#define NGG 12             // global pipeline groups (72 quads = 12 * 6)

// ---------------- device scratch (static, no allocation) ----------------
__device__ float4 g_W4ode[3 * NQ * HP];  // [mat][q][n] quad = W[4q..4q+3][n]
__device__ float4 g_W4u[NQ * HP];        // Wu quads
__device__ float g_WihT[E_ * 96];        // [e<300][g<90]
__device__ float g_WhhT[M_ * 96];        // [m<30][g<90]
__device__ float g_Wd1T[E_ * NP1];       // [k<300][n<300]
__device__ float g_Wd2T[E_ * VP];        // [n<300][v<8000]
__device__ float g_WembT[V_ * E_];       // [v][e]
__device__ float g_bu_pad[HP];
__device__ float g_bd1_pad[NP1];
__device__ int   g_len[B_];
__device__ float g_gall[(size_t)B_ * T_ * E_];        // [b][t][e]
__device__ float g_hemb[(size_t)(T_ - 1) * B_ * E_];  // [kk][b][e]
__device__ float g_d1[(size_t)(T_ - 1) * B_ * E_];    // [kk][b][e]

// dynamic smem layout in float4 units
#define S_SC   0                          // cached quads: 3 * CQ * HP = 11616
#define S_HS   (3 * CQ * HP)              // 11616
#define S_ACC  (S_HS  + HP)
#define S_YS   (S_ACC + HP)
#define S_AS   (S_YS  + HP)
#define S_BS   (S_AS  + HP)
#define S_G1   (S_BS  + HP)
#define S_G2   (S_G1  + 96)
#define SEQ_SMEM_F4 (S_G2 + 96)           // 13568 float4
#define SEQ_SMEM_BYTES (SEQ_SMEM_F4 * 16) // 217088

// ---------------- lengths normalization (int32 vs int64 auto-detect) ----------------
__global__ void prep_len(const int* __restrict__ Lraw) {
    int b = blockIdx.x * blockDim.x + threadIdx.x;
    if (b >= B_) return;
    int is64 = (Lraw[1] == 0);
    g_len[b] = is64 ? Lraw[2 * b] : Lraw[b];
}

// ---------------- fused weight prep ----------------
__global__ void prep_all(const float* __restrict__ W1, const float* __restrict__ W2,
                         const float* __restrict__ W3, const float* __restrict__ Wu,
                         const float* __restrict__ bu,
                         const float* __restrict__ Wih, const float* __restrict__ Whh,
                         const float* __restrict__ Wd1, const float* __restrict__ bd1) {
    int i = blockIdx.x * blockDim.x + threadIdx.x;
    if (i < 3 * NQ * HP) {
        int mat = i / (NQ * HP);
        int r = i - mat * (NQ * HP);
        int q = r / HP, n = r % HP;
        const float* W = (mat == 0) ? W1 : (mat == 1) ? W2 : W3;
        float4 v = make_float4(0.f, 0.f, 0.f, 0.f);
        if (n < H_) {
            int k = 4 * q;
            if (k + 0 < H_) v.x = W[n * H_ + k + 0];
            if (k + 1 < H_) v.y = W[n * H_ + k + 1];
            if (k + 2 < H_) v.z = W[n * H_ + k + 2];
            if (k + 3 < H_) v.w = W[n * H_ + k + 3];
        }
        g_W4ode[i] = v;
    }
    if (i < NQ * HP) {
        int q = i / HP, n = i % HP;
        float4 v = make_float4(0.f, 0.f, 0.f, 0.f);
        if (n < E_) {
            int k = 4 * q;
            if (k + 0 < H_) v.x = Wu[n * H_ + k + 0];
            if (k + 1 < H_) v.y = Wu[n * H_ + k + 1];
            if (k + 2 < H_) v.z = Wu[n * H_ + k + 2];
            if (k + 3 < H_) v.w = Wu[n * H_ + k + 3];
        }
        g_W4u[i] = v;
    }
    if (i < E_ * 96) {
        int e = i / 96, g = i % 96;
        g_WihT[i] = (g < 90) ? Wih[g * E_ + e] : 0.f;
    }
    if (i < M_ * 96) {
        int m = i / 96, g = i % 96;
        g_WhhT[i] = (g < 90) ? Whh[g * M_ + m] : 0.f;
    }
    if (i < E_ * NP1) {
        int k = i / NP1, n = i % NP1;
        g_Wd1T[i] = (n < E_) ? Wd1[n * E_ + k] : 0.f;
    }
    if (i < HP)  g_bu_pad[i]  = (i < E_) ? bu[i]  : 0.f;
    if (i < NP1) g_bd1_pad[i] = (i < E_) ? bd1[i] : 0.f;
}

__global__ void prep_wd2(const float* __restrict__ Wd2) {
    int i = blockIdx.x * blockDim.x + threadIdx.x;
    if (i >= E_ * VP) return;
    int n = i / VP, v = i % VP;
    g_Wd2T[i] = (v < V_) ? Wd2[v * E_ + n] : 0.f;
}

__global__ void prep_wemb(const float* __restrict__ Wemb) {
    int i = blockIdx.x * blockDim.x + threadIdx.x;
    if (i >= V_ * E_) return;
    int v = i / E_, e = i % E_;
    g_WembT[i] = Wemb[e * V_ + v];
}

// ---------------- sparse embedding (deterministic prefix-scan compaction) ----------------
__global__ void __launch_bounds__(256) embed_kernel(const float* __restrict__ codes,
                                                    const float* __restrict__ bemb) {
    __shared__ int idx[1024];
    __shared__ int cnts[256];
    __shared__ int total;
    int blk = blockIdx.x;               // blk = b*T_ + t
    int t = threadIdx.x;
    const float* crow = codes + (size_t)blk * V_;
    int base = t * 32;
    int c = 0;
#pragma unroll 4
    for (int j = 0; j < 32; j++) {
        int v = base + j;
        if (v < V_ && crow[v] != 0.f) c++;
    }
    cnts[t] = c;
    __syncthreads();
    for (int off = 1; off < 256; off <<= 1) {
        int val = cnts[t];
        int add = (t >= off) ? cnts[t - off] : 0;
        __syncthreads();
        cnts[t] = val + add;
        __syncthreads();
    }
    int p = cnts[t] - c;
    for (int j = 0; j < 32; j++) {
        int v = base + j;
        if (v < V_ && crow[v] != 0.f) {
            if (p < 1024) idx[p] = v;
            p++;
        }
    }
    if (t == 255) total = cnts[255];
    __syncthreads();
    int n = total > 1024 ? 1024 : total;
    for (int e = t; e < E_; e += 256) {
        float acc = bemb[e];
        for (int j = 0; j < n; j++) acc += g_WembT[idx[j] * E_ + e];
        g_gall[(size_t)blk * E_ + e] = acc;
    }
}

// ---------------- sequential ODE + GRU kernel ----------------
__device__ __forceinline__ void grp_fma(const float4* __restrict__ wb,
                                        const float4* __restrict__ xp,
                                        float& a0, float& a1, float& a2, float& a3) {
#pragma unroll
    for (int j = 0; j < 6; j++) {
        float4 w = wb[j];
        float4 x0 = xp[4 * j + 0], x1 = xp[4 * j + 1];
        float4 x2 = xp[4 * j + 2], x3 = xp[4 * j + 3];
        a0 = fmaf(w.x, x0.x, a0); a1 = fmaf(w.x, x0.y, a1);
        a2 = fmaf(w.x, x0.z, a2); a3 = fmaf(w.x, x0.w, a3);
        a0 = fmaf(w.y, x1.x, a0); a1 = fmaf(w.y, x1.y, a1);
        a2 = fmaf(w.y, x1.z, a2); a3 = fmaf(w.y, x1.w, a3);
        a0 = fmaf(w.z, x2.x, a0); a1 = fmaf(w.z, x2.y, a1);
        a2 = fmaf(w.z, x2.z, a2); a3 = fmaf(w.z, x2.w, a3);
        a0 = fmaf(w.w, x3.x, a0); a1 = fmaf(w.w, x3.y, a1);
        a2 = fmaf(w.w, x3.z, a2); a3 = fmaf(w.w, x3.w, a3);
    }
}

// One matmul stage. Quads 0..CQ-1 come from smem cache (or global for Wu),
// quads CQ..82 from global in 12 ping-pong-prefetched groups of 6, rotated
// per warp (g0) to spread L2 line demand. Quad 83 is all-zero: skipped.
template <bool TANH, bool BIAS>
__device__ __forceinline__ void mm_stage(const float4* __restrict__ W4,
                                         const float4* __restrict__ cache,
                                         const float4* __restrict__ xs,
                                         float4* __restrict__ ys,
                                         const float* __restrict__ bias,
                                         int tid, int g0) {
    float a0 = 0.f, a1 = 0.f, a2 = 0.f, a3 = 0.f;
    const float4* wg = W4 + tid;           // advance by q*HP
    float4 wA[6], wB[6];
    int g = g0;
    // preload global group g (hidden under the cached prologue)
    {
        const float4* p = wg + (size_t)(CQ + g * 6) * HP;
#pragma unroll
        for (int j = 0; j < 6; j++) wA[j] = p[j * HP];
    }
    // cached prologue: quads 0..CQ-1
#pragma unroll
    for (int q = 0; q < CQ; q++) {
        float4 w = cache ? cache[q * HP + tid] : wg[q * HP];
        const float4* xp = xs + 4 * q;
        float4 x0 = xp[0], x1 = xp[1], x2 = xp[2], x3 = xp[3];
        a0 = fmaf(w.x, x0.x, a0); a1 = fmaf(w.x, x0.y, a1);
        a2 = fmaf(w.x, x0.z, a2); a3 = fmaf(w.x, x0.w, a3);
        a0 = fmaf(w.y, x1.x, a0); a1 = fmaf(w.y, x1.y, a1);
        a2 = fmaf(w.y, x1.z, a2); a3 = fmaf(w.y, x1.w, a3);
        a0 = fmaf(w.z, x2.x, a0); a1 = fmaf(w.z, x2.y, a1);
        a2 = fmaf(w.z, x2.z, a2); a3 = fmaf(w.z, x2.w, a3);
        a0 = fmaf(w.w, x3.x, a0); a1 = fmaf(w.w, x3.y, a1);
        a2 = fmaf(w.w, x3.z, a2); a3 = fmaf(w.w, x3.w, a3);
    }
    // pipelined global groups: 5 pairs + 1 final pair
#pragma unroll 1
    for (int it = 0; it < 5; it++) {
        int g1 = g + 1; if (g1 >= NGG) g1 = 0;
        {
            const float4* p = wg + (size_t)(CQ + g1 * 6) * HP;
#pragma unroll
            for (int j = 0; j < 6; j++) wB[j] = p[j * HP];
        }
        grp_fma(wA, xs + 4 * (CQ + g * 6), a0, a1, a2, a3);
        int g2 = g1 + 1; if (g2 >= NGG) g2 = 0;
        {
            const float4* p = wg + (size_t)(CQ + g2 * 6) * HP;
#pragma unroll
            for (int j = 0; j < 6; j++) wA[j] = p[j * HP];
        }
        grp_fma(wB, xs + 4 * (CQ + g1 * 6), a0, a1, a2, a3);
        g = g2;
    }
    {
        int g1 = g + 1; if (g1 >= NGG) g1 = 0;
        {
            const float4* p = wg + (size_t)(CQ + g1 * 6) * HP;
#pragma unroll
            for (int j = 0; j < 6; j++) wB[j] = p[j * HP];
        }
        grp_fma(wA, xs + 4 * (CQ + g * 6), a0, a1, a2, a3);
        grp_fma(wB, xs + 4 * (CQ + g1 * 6), a0, a1, a2, a3);
    }
    if (BIAS) { float bv = bias[tid]; a0 += bv; a1 += bv; a2 += bv; a3 += bv; }
    if (TANH) { a0 = tanhf(a0); a1 = tanhf(a1); a2 = tanhf(a2); a3 = tanhf(a3); }
    ys[tid] = make_float4(a0, a1, a2, a3);
    __syncthreads();
}

__device__ __forceinline__ void ode_f(const float4* sc, const float4* src,
                                      float4* bufA, float4* bufB, int tid, int g0) {
    mm_stage<true, false>(g_W4ode,              sc,               src,  bufA, nullptr, tid, g0);
    mm_stage<true, false>(g_W4ode + NQ * HP,    sc + CQ * HP,     bufA, bufB, nullptr, tid, g0);
    mm_stage<true, false>(g_W4ode + 2 * NQ * HP, sc + 2 * CQ * HP, bufB, bufA, nullptr, tid, g0);
}

__device__ __forceinline__ float sigf(float x) { return 1.f / (1.f + expf(-x)); }

__global__ void __launch_bounds__(HP, 1) seq_kernel(const float* __restrict__ b_ih,
                                                    const float* __restrict__ b_hh) {
    extern __shared__ float4 sm4[];
    float4* SC  = sm4 + S_SC;
    float4* Hs  = sm4 + S_HS;
    float4* ACC = sm4 + S_ACC;
    float4* Ys  = sm4 + S_YS;
    float4* As  = sm4 + S_AS;
    float4* Bs  = sm4 + S_BS;
    float4* G1  = sm4 + S_G1;
    float4* G2  = sm4 + S_G2;
    int tid = threadIdx.x;
    int b0 = blockIdx.x * 4;
    int g0 = (blockIdx.x * 11 + (tid >> 5)) % NGG;    // per-warp rotation phase

    // fill smem weight cache: quads 0..CQ-1 of W1/W2/W3
    for (int i = tid; i < 3 * CQ * HP; i += HP) {
        int mat = i / (CQ * HP);
        int r = i - mat * (CQ * HP);
        SC[i] = g_W4ode[mat * (NQ * HP) + r];
    }

    // h0 = [zeros(M), g_all[:,0,:]]
    {
        float4 h = make_float4(0.f, 0.f, 0.f, 0.f);
        if (tid >= M_ && tid < H_) {
            int e = tid - M_;
            h.x = g_gall[((size_t)(b0 + 0) * T_ + 0) * E_ + e];
            h.y = g_gall[((size_t)(b0 + 1) * T_ + 0) * E_ + e];
            h.z = g_gall[((size_t)(b0 + 2) * T_ + 0) * E_ + e];
            h.w = g_gall[((size_t)(b0 + 3) * T_ + 0) * E_ + e];
        }
        Hs[tid] = h;
        __syncthreads();
    }

    for (int k = 1; k < T_; k++) {
        // ---- RK4 with N_STEPS substeps ----
        for (int s = 0; s < NSTEPS; s++) {
            ode_f(SC, Hs, As, Bs, tid, g0);                      // k1 -> As
            {
                float4 a = As[tid], h = Hs[tid];
                ACC[tid] = a;
                Ys[tid] = make_float4(h.x + 0.5f * DT_ * a.x, h.y + 0.5f * DT_ * a.y,
                                      h.z + 0.5f * DT_ * a.z, h.w + 0.5f * DT_ * a.w);
                __syncthreads();
            }
            ode_f(SC, Ys, As, Bs, tid, g0);                      // k2 -> As
            {
                float4 a = As[tid], h = Hs[tid], c = ACC[tid];
                ACC[tid] = make_float4(c.x + 2.f * a.x, c.y + 2.f * a.y,
                                       c.z + 2.f * a.z, c.w + 2.f * a.w);
                Ys[tid] = make_float4(h.x + 0.5f * DT_ * a.x, h.y + 0.5f * DT_ * a.y,
                                      h.z + 0.5f * DT_ * a.z, h.w + 0.5f * DT_ * a.w);
                __syncthreads();
            }
            ode_f(SC, Ys, As, Bs, tid, g0);                      // k3 -> As
            {
                float4 a = As[tid], h = Hs[tid], c = ACC[tid];
                ACC[tid] = make_float4(c.x + 2.f * a.x, c.y + 2.f * a.y,
                                       c.z + 2.f * a.z, c.w + 2.f * a.w);
                Ys[tid] = make_float4(h.x + DT_ * a.x, h.y + DT_ * a.y,
                                      h.z + DT_ * a.z, h.w + DT_ * a.w);
                __syncthreads();
            }
            ode_f(SC, Ys, As, Bs, tid, g0);                      // k4 -> As
            {
                const float c6 = DT_ / 6.f;
                float4 a = As[tid], h = Hs[tid], c = ACC[tid];
                Hs[tid] = make_float4(h.x + c6 * (c.x + a.x), h.y + c6 * (c.y + a.y),
                                      h.z + c6 * (c.z + a.z), h.w + c6 * (c.w + a.w));
                __syncthreads();
            }
        }

        // ---- dump h_emb for the decoupled decoder; build cin = [h_mem, g_k] ----
        if (tid < E_) {
            float4 v = Hs[M_ + tid];
            size_t base = ((size_t)(k - 1) * B_ + b0) * E_ + tid;
            g_hemb[base]          = v.x;
            g_hemb[base + E_]     = v.y;
            g_hemb[base + 2 * E_] = v.z;
            g_hemb[base + 3 * E_] = v.w;
        }
        {
            float4 c = make_float4(0.f, 0.f, 0.f, 0.f);
            if (tid < M_) c = Hs[tid];
            else if (tid < H_) {
                int e = tid - M_;
                c.x = g_gall[((size_t)(b0 + 0) * T_ + k) * E_ + e];
                c.y = g_gall[((size_t)(b0 + 1) * T_ + k) * E_ + e];
                c.z = g_gall[((size_t)(b0 + 2) * T_ + k) * E_ + e];
                c.w = g_gall[((size_t)(b0 + 3) * T_ + k) * E_ + e];
            }
            Ys[tid] = c;
            __syncthreads();
        }

        // ---- x = cin @ W_u^T + b_u  -> As (no smem cache for Wu) ----
        mm_stage<false, true>(g_W4u, nullptr, Ys, As, g_bu_pad, tid, g0);

        // ---- GRU gates ----
        if (tid < 96) {
            int g = tid;
            float bb = (g < 90) ? b_ih[g] : 0.f;
            float4 a = make_float4(bb, bb, bb, bb);
#pragma unroll 4
            for (int e = 0; e < E_; e++) {
                float w = g_WihT[e * 96 + g];
                float4 x = As[e];
                a.x = fmaf(w, x.x, a.x); a.y = fmaf(w, x.y, a.y);
                a.z = fmaf(w, x.z, a.z); a.w = fmaf(w, x.w, a.w);
            }
            G1[g] = a;
        } else if (tid < 192) {
            int g = tid - 96;
            float bb = (g < 90) ? b_hh[g] : 0.f;
            float4 a = make_float4(bb, bb, bb, bb);
#pragma unroll
            for (int m = 0; m < M_; m++) {
                float w = g_WhhT[m * 96 + g];
                float4 x = Hs[m];
                a.x = fmaf(w, x.x, a.x); a.y = fmaf(w, x.y, a.y);
                a.z = fmaf(w, x.z, a.z); a.w = fmaf(w, x.w, a.w);
            }
            G2[g] = a;
        }
        __syncthreads();

        if (tid < M_) {
            int m = tid;
            float4 xr = G1[m],          hr = G2[m];
            float4 xz = G1[M_ + m],     hz = G2[M_ + m];
            float4 xn = G1[2 * M_ + m], hn = G2[2 * M_ + m];
            float4 ho = Hs[m];
            float4 hv;
            { float r = sigf(xr.x + hr.x), z = sigf(xz.x + hz.x);
              float t = tanhf(xn.x + r * hn.x); hv.x = (1.f - z) * t + z * ho.x; }
            { float r = sigf(xr.y + hr.y), z = sigf(xz.y + hz.y);
              float t = tanhf(xn.y + r * hn.y); hv.y = (1.f - z) * t + z * ho.y; }
            { float r = sigf(xr.z + hr.z), z = sigf(xz.z + hz.z);
              float t = tanhf(xn.z + r * hn.z); hv.z = (1.f - z) * t + z * ho.z; }
            { float r = sigf(xr.w + hr.w), z = sigf(xz.w + hz.w);
              float t = tanhf(xn.w + r * hn.w); hv.w = (1.f - z) * t + z * ho.w; }
            Hs[m] = hv;
        }
        __syncthreads();
    }
}

// ---------------- decoder stage 1: d1 = leaky_relu(hemb @ W_d1^T + b_d1) ----------------
__global__ void __launch_bounds__(NP1) d1_kernel() {
    __shared__ float4 Xs[E_];
    int tid = threadIdx.x;
    int i0 = blockIdx.x * 4;
    if (tid < E_) {
        float4 v;
        v.x = g_hemb[(size_t)(i0 + 0) * E_ + tid];
        v.y = g_hemb[(size_t)(i0 + 1) * E_ + tid];
        v.z = g_hemb[(size_t)(i0 + 2) * E_ + tid];
        v.w = g_hemb[(size_t)(i0 + 3) * E_ + tid];
        Xs[tid] = v;
    }
    __syncthreads();
    int n = tid;
    float bv = g_bd1_pad[n];
    float a0 = bv, a1 = bv, a2 = bv, a3 = bv;
#pragma unroll 5
    for (int kk = 0; kk < E_; kk++) {
        float w = g_Wd1T[kk * NP1 + n];
        float4 x = Xs[kk];
        a0 = fmaf(w, x.x, a0); a1 = fmaf(w, x.y, a1);
        a2 = fmaf(w, x.z, a2); a3 = fmaf(w, x.w, a3);
    }
    a0 = a0 >= 0.f ? a0 : 0.01f * a0;
    a1 = a1 >= 0.f ? a1 : 0.01f * a1;
    a2 = a2 >= 0.f ? a2 : 0.01f * a2;
    a3 = a3 >= 0.f ? a3 : 0.01f * a3;
    if (n < E_) {
        g_d1[(size_t)(i0 + 0) * E_ + n] = a0;
        g_d1[(size_t)(i0 + 1) * E_ + n] = a1;
        g_d1[(size_t)(i0 + 2) * E_ + n] = a2;
        g_d1[(size_t)(i0 + 3) * E_ + n] = a3;
    }
}

// ---------------- decoder stage 2: logits = d1 @ W_d2^T + b_d2 (masked) ----------------
#define AS4 9   // A_s row stride in float4 (36 floats)
__global__ void __launch_bounds__(256) logits_kernel(const float* __restrict__ bd2,
                                                     float* __restrict__ out) {
    __shared__ float4 A_s4[E_ * AS4];
    __shared__ int vld[32];
    float* A_s = (float*)A_s4;
    int tid = threadIdx.x;
    int i0 = blockIdx.x * 32;                 // row tile (i = kk*512 + b)
    int vt = blockIdx.y * 256;                // v tile

    if (tid < 32) {
        int i = i0 + tid;
        int kk = i >> 9, b = i & 511;
        vld[tid] = ((kk + 1) < g_len[b]) ? 1 : 0;
    }
    int any = __syncthreads_or(
        tid < 32 ? ((((i0 + tid) >> 9) + 1) < g_len[(i0 + tid) & 511]) : 0);

    int vq = vt + (tid & 63) * 4;
    int g2 = (tid >> 6) * 2;
    int rb = (tid >> 6) * 8;
    float4 acc[8];
#pragma unroll
    for (int r = 0; r < 8; r++) acc[r] = make_float4(0.f, 0.f, 0.f, 0.f);

    if (any) {
        for (int idx = tid; idx < 32 * E_; idx += 256) {
            int r = idx / E_, kk = idx - r * E_;
            A_s[kk * 36 + r] = g_d1[(size_t)(i0 + r) * E_ + kk];
        }
        __syncthreads();
        if (vq < V_) {
#pragma unroll 2
            for (int kk = 0; kk < E_; kk++) {
                float4 w = *(const float4*)&g_Wd2T[(size_t)kk * VP + vq];
                float4 xa = A_s4[kk * AS4 + g2];
                float4 xb = A_s4[kk * AS4 + g2 + 1];
                float ar[8] = {xa.x, xa.y, xa.z, xa.w, xb.x, xb.y, xb.z, xb.w};
#pragma unroll
                for (int r = 0; r < 8; r++) {
                    acc[r].x = fmaf(ar[r], w.x, acc[r].x);
                    acc[r].y = fmaf(ar[r], w.y, acc[r].y);
                    acc[r].z = fmaf(ar[r], w.z, acc[r].z);
                    acc[r].w = fmaf(ar[r], w.w, acc[r].w);
                }
            }
        }
    }

    if (vq < V_) {
        float4 bb = *(const float4*)&bd2[vq];
        const float4 zero = make_float4(0.f, 0.f, 0.f, 0.f);
#pragma unroll
        for (int r = 0; r < 8; r++) {
            int i = i0 + rb + r;
            int kk = i >> 9, b = i & 511;
            float4 o;
            if (vld[rb + r]) {
                o = make_float4(acc[r].x + bb.x, acc[r].y + bb.y,
                                acc[r].z + bb.z, acc[r].w + bb.w);
            } else {
                o = zero;
            }
            *(float4*)&out[((size_t)b * (T_ - 1) + kk) * V_ + vq] = o;
        }
    }
}

// ---------------- launch ----------------
extern "C" void kernel_launch(void* const* d_in, const int* in_sizes, int n_in,
                              void* d_out, int out_size) {
    (void)in_sizes; (void)n_in; (void)out_size;
    const float* codes   = (const float*)d_in[1];
    const int*   lengths = (const int*)d_in[2];
    const float* W_emb   = (const float*)d_in[3];
    const float* b_emb   = (const float*)d_in[4];
    const float* W1      = (const float*)d_in[5];
    const float* W2      = (const float*)d_in[6];
    const float* W3      = (const float*)d_in[7];
    const float* W_u     = (const float*)d_in[8];
    const float* b_u     = (const float*)d_in[9];
    const float* W_ih    = (const float*)d_in[10];
    const float* W_hh    = (const float*)d_in[11];
    const float* b_ih    = (const float*)d_in[12];
    const float* b_hh    = (const float*)d_in[13];
    const float* W_d1    = (const float*)d_in[14];
    const float* b_d1    = (const float*)d_in[15];
    const float* W_d2    = (const float*)d_in[16];
    const float* b_d2    = (const float*)d_in[17];
    float* out = (float*)d_out;

    static int smem_set = 0;
    if (!smem_set) {
        cudaFuncSetAttribute(seq_kernel, cudaFuncAttributeMaxDynamicSharedMemorySize,
                             SEQ_SMEM_BYTES);
        smem_set = 1;
    }

    // seq_kernel is my launch #4 = overall #6 for ncu -s 5 -c 1.
    prep_wemb<<<(V_ * E_ + 255) / 256, 256>>>(W_emb);                          // 1
    prep_all<<<(E_ * NP1 + 255) / 256, 256>>>(W1, W2, W3, W_u, b_u,
                                              W_ih, W_hh, W_d1, b_d1);         // 2
    embed_kernel<<<B_ * T_, 256>>>(codes, b_emb);                              // 3
    seq_kernel<<<B_ / 4, HP, SEQ_SMEM_BYTES>>>(b_ih, b_hh);                    // 4 <- profiled
    prep_wd2<<<(E_ * VP + 255) / 256, 256>>>(W_d2);                            // 5
    prep_len<<<2, 256>>>(lengths);                                             // 6
    d1_kernel<<<((T_ - 1) * B_) / 4, NP1>>>();                                 // 7
    dim3 lgrid(((T_ - 1) * B_) / 32, (V_ + 255) / 256);
    logits_kernel<<<lgrid, 256>>>(b_d2, out);                                  // 8
}

// round 16
// speedup vs baseline: 2.0716x; 1.0349x over previous
#include <cuda_runtime.h>
#include <math.h>

#define B_  512
#define T_  24
#define V_  8000
#define E_  300
#define M_  30
#define H_  330
#define HP  352            // padded n-columns (11 warps)
#define NSTEPS 8
#define DT_ 0.875f         // 7/8
#define VP  8192           // padded V for W_d2T
#define NP1 320            // padded N for d1 stage
#define NQ  84             // k-quads per matrix (K padded to 336)
#define QH  42             // quads per k-half
#define NGR 7              // pipeline groups per half (42 = 7 * 6)
#define NROWS ((T_ - 1) * B_)   // 11776 decoder rows

// ---------------- device scratch (static, no allocation) ----------------
__device__ float4 g_W4ode[3 * NQ * HP];  // [mat][q][n] quad = W[4q..4q+3][n]
__device__ float4 g_W4u[NQ * HP];        // Wu quads
__device__ float g_WihT[E_ * 96];        // [e<300][g<90]
__device__ float g_WhhT[M_ * 96];        // [m<30][g<90]
__device__ float g_Wd1T[E_ * NP1];       // [k<300][n<300]
__device__ float g_Wd2T[E_ * VP];        // [n<300][v<8000]
__device__ float g_WembT[V_ * E_];       // [v][e]
__device__ float g_bu_pad[HP];
__device__ float g_bd1_pad[NP1];
__device__ int   g_len[B_];
__device__ int   g_rows[NROWS];          // compacted valid decoder rows
__device__ int   g_nvalid;
__device__ float g_gall[(size_t)B_ * T_ * E_];        // [b][t][e]
__device__ float g_hemb[(size_t)NROWS * E_];          // [kk][b][e]
__device__ float g_d1[(size_t)NROWS * E_];            // [kk][b][e]

// ---------------- lengths normalization (int32 vs int64 auto-detect) ----------------
__global__ void prep_len(const int* __restrict__ Lraw) {
    int b = blockIdx.x * blockDim.x + threadIdx.x;
    if (b >= B_) return;
    int is64 = (Lraw[1] == 0);
    g_len[b] = is64 ? Lraw[2 * b] : Lraw[b];
}

// ---------------- compacted valid-row list (deterministic scan) ----------------
__global__ void __launch_bounds__(1024) rowlist_kernel() {
    __shared__ int cnts[1024];
    int t = threadIdx.x;
    int lo = t * 12, hi = lo + 12;
    if (hi > NROWS) hi = NROWS;
    int c = 0;
    for (int i = lo; i < hi; i++) {
        int kk = i >> 9, b = i & 511;
        if ((kk + 1) < g_len[b]) c++;
    }
    cnts[t] = c;
    __syncthreads();
    for (int off = 1; off < 1024; off <<= 1) {
        int val = cnts[t];
        int add = (t >= off) ? cnts[t - off] : 0;
        __syncthreads();
        cnts[t] = val + add;
        __syncthreads();
    }
    int p = cnts[t] - c;
    for (int i = lo; i < hi; i++) {
        int kk = i >> 9, b = i & 511;
        if ((kk + 1) < g_len[b]) g_rows[p++] = i;
    }
    if (t == 1023) g_nvalid = cnts[1023];
}

// ---------------- zero-fill invalid decoder rows ----------------
__global__ void __launch_bounds__(256) zerofill_kernel(float* __restrict__ out) {
    int i = blockIdx.x;
    int kk = i >> 9, b = i & 511;
    if ((kk + 1) < g_len[b]) return;
    float4* row = (float4*)(out + ((size_t)b * (T_ - 1) + kk) * V_);
    const float4 z = make_float4(0.f, 0.f, 0.f, 0.f);
    for (int j = threadIdx.x; j < V_ / 4; j += 256) row[j] = z;
}

// ---------------- fused weight prep ----------------
__global__ void prep_all(const float* __restrict__ W1, const float* __restrict__ W2,
                         const float* __restrict__ W3, const float* __restrict__ Wu,
                         const float* __restrict__ bu,
                         const float* __restrict__ Wih, const float* __restrict__ Whh,
                         const float* __restrict__ Wd1, const float* __restrict__ bd1) {
    int i = blockIdx.x * blockDim.x + threadIdx.x;
    if (i < 3 * NQ * HP) {
        int mat = i / (NQ * HP);
        int r = i - mat * (NQ * HP);
        int q = r / HP, n = r % HP;
        const float* W = (mat == 0) ? W1 : (mat == 1) ? W2 : W3;
        float4 v = make_float4(0.f, 0.f, 0.f, 0.f);
        if (n < H_) {
            int k = 4 * q;
            if (k + 0 < H_) v.x = W[n * H_ + k + 0];
            if (k + 1 < H_) v.y = W[n * H_ + k + 1];
            if (k + 2 < H_) v.z = W[n * H_ + k + 2];
            if (k + 3 < H_) v.w = W[n * H_ + k + 3];
        }
        g_W4ode[i] = v;
    }
    if (i < NQ * HP) {
        int q = i / HP, n = i % HP;
        float4 v = make_float4(0.f, 0.f, 0.f, 0.f);
        if (n < E_) {
            int k = 4 * q;
            if (k + 0 < H_) v.x = Wu[n * H_ + k + 0];
            if (k + 1 < H_) v.y = Wu[n * H_ + k + 1];
            if (k + 2 < H_) v.z = Wu[n * H_ + k + 2];
            if (k + 3 < H_) v.w = Wu[n * H_ + k + 3];
        }
        g_W4u[i] = v;
    }
    if (i < E_ * 96) {
        int e = i / 96, g = i % 96;
        g_WihT[i] = (g < 90) ? Wih[g * E_ + e] : 0.f;
    }
    if (i < M_ * 96) {
        int m = i / 96, g = i % 96;
        g_WhhT[i] = (g < 90) ? Whh[g * M_ + m] : 0.f;
    }
    if (i < E_ * NP1) {
        int k = i / NP1, n = i % NP1;
        g_Wd1T[i] = (n < E_) ? Wd1[n * E_ + k] : 0.f;
    }
    if (i < HP)  g_bu_pad[i]  = (i < E_) ? bu[i]  : 0.f;
    if (i < NP1) g_bd1_pad[i] = (i < E_) ? bd1[i] : 0.f;
}

__global__ void prep_wd2(const float* __restrict__ Wd2) {
    int i = blockIdx.x * blockDim.x + threadIdx.x;
    if (i >= E_ * VP) return;
    int n = i / VP, v = i % VP;
    g_Wd2T[i] = (v < V_) ? Wd2[v * E_ + n] : 0.f;
}

__global__ void prep_wemb(const float* __restrict__ Wemb) {
    int i = blockIdx.x * blockDim.x + threadIdx.x;
    if (i >= V_ * E_) return;
    int v = i / E_, e = i % E_;
    g_WembT[i] = Wemb[e * V_ + v];
}

// ---------------- sparse embedding (deterministic prefix-scan compaction) ----------------
__global__ void __launch_bounds__(256) embed_kernel(const float* __restrict__ codes,
                                                    const float* __restrict__ bemb) {
    __shared__ int idx[1024];
    __shared__ int cnts[256];
    __shared__ int total;
    int blk = blockIdx.x;               // blk = b*T_ + t
    int t = threadIdx.x;
    const float* crow = codes + (size_t)blk * V_;
    int base = t * 32;
    int c = 0;
#pragma unroll 4
    for (int j = 0; j < 32; j++) {
        int v = base + j;
        if (v < V_ && crow[v] != 0.f) c++;
    }
    cnts[t] = c;
    __syncthreads();
    for (int off = 1; off < 256; off <<= 1) {
        int val = cnts[t];
        int add = (t >= off) ? cnts[t - off] : 0;
        __syncthreads();
        cnts[t] = val + add;
        __syncthreads();
    }
    int p = cnts[t] - c;
    for (int j = 0; j < 32; j++) {
        int v = base + j;
        if (v < V_ && crow[v] != 0.f) {
            if (p < 1024) idx[p] = v;
            p++;
        }
    }
    if (t == 255) total = cnts[255];
    __syncthreads();
    int n = total > 1024 ? 1024 : total;
    for (int e = t; e < E_; e += 256) {
        float acc = bemb[e];
        for (int j = 0; j < n; j++) acc += g_WembT[idx[j] * E_ + e];
        g_gall[(size_t)blk * E_ + e] = acc;
    }
}

// ---------------- sequential ODE + GRU kernel (704 threads, split-K(2)) ----------------
__device__ __forceinline__ void grp_fma6(const float4* __restrict__ wb,
                                         const float4* __restrict__ xp,
                                         float& a0, float& a1, float& a2, float& a3) {
#pragma unroll
    for (int j = 0; j < 6; j++) {
        float4 w = wb[j];
        float4 x0 = xp[4 * j + 0], x1 = xp[4 * j + 1];
        float4 x2 = xp[4 * j + 2], x3 = xp[4 * j + 3];
        a0 = fmaf(w.x, x0.x, a0); a1 = fmaf(w.x, x0.y, a1);
        a2 = fmaf(w.x, x0.z, a2); a3 = fmaf(w.x, x0.w, a3);
        a0 = fmaf(w.y, x1.x, a0); a1 = fmaf(w.y, x1.y, a1);
        a2 = fmaf(w.y, x1.z, a2); a3 = fmaf(w.y, x1.w, a3);
        a0 = fmaf(w.z, x2.x, a0); a1 = fmaf(w.z, x2.y, a1);
        a2 = fmaf(w.z, x2.z, a2); a3 = fmaf(w.z, x2.w, a3);
        a0 = fmaf(w.w, x3.x, a0); a1 = fmaf(w.w, x3.y, a1);
        a2 = fmaf(w.w, x3.z, a2); a3 = fmaf(w.w, x3.w, a3);
    }
}

// Split-K matmul stage: kh half owns 42 quads (7 ping-pong groups of 6),
// rotated per warp (g0). kh=1 deposits partials; kh=0 combines (+bias/tanh).
template <bool TANH, bool BIAS>
__device__ __forceinline__ void mm2(const float4* __restrict__ W4,
                                    const float4* __restrict__ xs,
                                    float4* __restrict__ ys,
                                    float4* __restrict__ part,
                                    const float* __restrict__ bias,
                                    int n, int kh, int g0) {
    float a0 = 0.f, a1 = 0.f, a2 = 0.f, a3 = 0.f;
    const float4* wk = W4 + (size_t)(kh * QH) * HP + n;   // quad qg at wk[qg*6.. ] stride HP
    const float4* xk = xs + kh * (QH * 4);                // x for local quad qg at xk[4*qg]
    float4 wA[6], wB[6];
    int g = g0;
    {
        const float4* p = wk + (size_t)(g * 6) * HP;
#pragma unroll
        for (int j = 0; j < 6; j++) wA[j] = p[j * HP];
    }
#pragma unroll 1
    for (int it = 0; it < 3; it++) {
        int g1 = g + 1; if (g1 >= NGR) g1 = 0;
        {
            const float4* p = wk + (size_t)(g1 * 6) * HP;
#pragma unroll
            for (int j = 0; j < 6; j++) wB[j] = p[j * HP];
        }
        grp_fma6(wA, xk + 24 * g, a0, a1, a2, a3);
        int g2 = g1 + 1; if (g2 >= NGR) g2 = 0;
        {
            const float4* p = wk + (size_t)(g2 * 6) * HP;
#pragma unroll
            for (int j = 0; j < 6; j++) wA[j] = p[j * HP];
        }
        grp_fma6(wB, xk + 24 * g1, a0, a1, a2, a3);
        g = g2;
    }
    grp_fma6(wA, xk + 24 * g, a0, a1, a2, a3);
    if (kh) part[n] = make_float4(a0, a1, a2, a3);
    __syncthreads();
    if (!kh) {
        float4 p = part[n];
        a0 += p.x; a1 += p.y; a2 += p.z; a3 += p.w;
        if (BIAS) { float bv = bias[n]; a0 += bv; a1 += bv; a2 += bv; a3 += bv; }
        if (TANH) { a0 = tanhf(a0); a1 = tanhf(a1); a2 = tanhf(a2); a3 = tanhf(a3); }
        ys[n] = make_float4(a0, a1, a2, a3);
    }
    __syncthreads();
}

__device__ __forceinline__ void ode_f(const float4* src, float4* bufA, float4* bufB,
                                      float4* part, int n, int kh, int g0) {
    mm2<true, false>(g_W4ode,               src,  bufA, part, nullptr, n, kh, g0);
    mm2<true, false>(g_W4ode + NQ * HP,     bufA, bufB, part, nullptr, n, kh, g0);
    mm2<true, false>(g_W4ode + 2 * NQ * HP, bufB, bufA, part, nullptr, n, kh, g0);
}

__device__ __forceinline__ float sigf(float x) { return 1.f / (1.f + expf(-x)); }

__global__ void __launch_bounds__(2 * HP, 1) seq_kernel(const float* __restrict__ b_ih,
                                                        const float* __restrict__ b_hh) {
    __shared__ float4 Hs[HP], ACC[HP], Ys[HP], As[HP], Bs[HP], Ps[HP];
    __shared__ float4 G1[96], G2[96];
    int tid = threadIdx.x;
    int kh = tid >= HP;
    int n  = tid - kh * HP;
    int b0 = blockIdx.x * 4;
    int g0 = (blockIdx.x * 22 + (tid >> 5)) % NGR;    // per-warp rotation phase

    // h0 = [zeros(M), g_all[:,0,:]]
    if (!kh) {
        float4 h = make_float4(0.f, 0.f, 0.f, 0.f);
        if (n >= M_ && n < H_) {
            int e = n - M_;
            h.x = g_gall[((size_t)(b0 + 0) * T_ + 0) * E_ + e];
            h.y = g_gall[((size_t)(b0 + 1) * T_ + 0) * E_ + e];
            h.z = g_gall[((size_t)(b0 + 2) * T_ + 0) * E_ + e];
            h.w = g_gall[((size_t)(b0 + 3) * T_ + 0) * E_ + e];
        }
        Hs[n] = h;
    }
    __syncthreads();

    for (int k = 1; k < T_; k++) {
        // ---- RK4 with N_STEPS substeps ----
        for (int s = 0; s < NSTEPS; s++) {
            ode_f(Hs, As, Bs, Ps, n, kh, g0);                    // k1 -> As
            if (!kh) {
                float4 a = As[n], h = Hs[n];
                ACC[n] = a;
                Ys[n] = make_float4(h.x + 0.5f * DT_ * a.x, h.y + 0.5f * DT_ * a.y,
                                    h.z + 0.5f * DT_ * a.z, h.w + 0.5f * DT_ * a.w);
            }
            __syncthreads();
            ode_f(Ys, As, Bs, Ps, n, kh, g0);                    // k2 -> As
            if (!kh) {
                float4 a = As[n], h = Hs[n], c = ACC[n];
                ACC[n] = make_float4(c.x + 2.f * a.x, c.y + 2.f * a.y,
                                     c.z + 2.f * a.z, c.w + 2.f * a.w);
                Ys[n] = make_float4(h.x + 0.5f * DT_ * a.x, h.y + 0.5f * DT_ * a.y,
                                    h.z + 0.5f * DT_ * a.z, h.w + 0.5f * DT_ * a.w);
            }
            __syncthreads();
            ode_f(Ys, As, Bs, Ps, n, kh, g0);                    // k3 -> As
            if (!kh) {
                float4 a = As[n], h = Hs[n], c = ACC[n];
                ACC[n] = make_float4(c.x + 2.f * a.x, c.y + 2.f * a.y,
                                     c.z + 2.f * a.z, c.w + 2.f * a.w);
                Ys[n] = make_float4(h.x + DT_ * a.x, h.y + DT_ * a.y,
                                    h.z + DT_ * a.z, h.w + DT_ * a.w);
            }
            __syncthreads();
            ode_f(Ys, As, Bs, Ps, n, kh, g0);                    // k4 -> As
            if (!kh) {
                const float c6 = DT_ / 6.f;
                float4 a = As[n], h = Hs[n], c = ACC[n];
                Hs[n] = make_float4(h.x + c6 * (c.x + a.x), h.y + c6 * (c.y + a.y),
                                    h.z + c6 * (c.z + a.z), h.w + c6 * (c.w + a.w));
            }
            __syncthreads();
        }

        // ---- dump h_emb for the decoupled decoder; build cin = [h_mem, g_k] ----
        if (!kh) {
            if (n < E_) {
                float4 v = Hs[M_ + n];
                size_t base = ((size_t)(k - 1) * B_ + b0) * E_ + n;
                g_hemb[base]          = v.x;
                g_hemb[base + E_]     = v.y;
                g_hemb[base + 2 * E_] = v.z;
                g_hemb[base + 3 * E_] = v.w;
            }
            float4 c = make_float4(0.f, 0.f, 0.f, 0.f);
            if (n < M_) c = Hs[n];
            else if (n < H_) {
                int e = n - M_;
                c.x = g_gall[((size_t)(b0 + 0) * T_ + k) * E_ + e];
                c.y = g_gall[((size_t)(b0 + 1) * T_ + k) * E_ + e];
                c.z = g_gall[((size_t)(b0 + 2) * T_ + k) * E_ + e];
                c.w = g_gall[((size_t)(b0 + 3) * T_ + k) * E_ + e];
            }
            Ys[n] = c;
        }
        __syncthreads();

        // ---- x = cin @ W_u^T + b_u  -> As ----
        mm2<false, true>(g_W4u, Ys, As, Ps, g_bu_pad, n, kh, g0);

        // ---- GRU gates (low warps; inputs ready after mm2's final barrier) ----
        if (tid < 96) {
            int g = tid;
            float bb = (g < 90) ? b_ih[g] : 0.f;
            float4 a = make_float4(bb, bb, bb, bb);
#pragma unroll 4
            for (int e = 0; e < E_; e++) {
                float w = g_WihT[e * 96 + g];
                float4 x = As[e];
                a.x = fmaf(w, x.x, a.x); a.y = fmaf(w, x.y, a.y);
                a.z = fmaf(w, x.z, a.z); a.w = fmaf(w, x.w, a.w);
            }
            G1[g] = a;
        } else if (tid < 192) {
            int g = tid - 96;
            float bb = (g < 90) ? b_hh[g] : 0.f;
            float4 a = make_float4(bb, bb, bb, bb);
#pragma unroll
            for (int m = 0; m < M_; m++) {
                float w = g_WhhT[m * 96 + g];
                float4 x = Hs[m];
                a.x = fmaf(w, x.x, a.x); a.y = fmaf(w, x.y, a.y);
                a.z = fmaf(w, x.z, a.z); a.w = fmaf(w, x.w, a.w);
            }
            G2[g] = a;
        }
        __syncthreads();

        if (tid < M_) {
            int m = tid;
            float4 xr = G1[m],          hr = G2[m];
            float4 xz = G1[M_ + m],     hz = G2[M_ + m];
            float4 xn = G1[2 * M_ + m], hn = G2[2 * M_ + m];
            float4 ho = Hs[m];
            float4 hv;
            { float r = sigf(xr.x + hr.x), z = sigf(xz.x + hz.x);
              float t = tanhf(xn.x + r * hn.x); hv.x = (1.f - z) * t + z * ho.x; }
            { float r = sigf(xr.y + hr.y), z = sigf(xz.y + hz.y);
              float t = tanhf(xn.y + r * hn.y); hv.y = (1.f - z) * t + z * ho.y; }
            { float r = sigf(xr.z + hr.z), z = sigf(xz.z + hz.z);
              float t = tanhf(xn.z + r * hn.z); hv.z = (1.f - z) * t + z * ho.z; }
            { float r = sigf(xr.w + hr.w), z = sigf(xz.w + hz.w);
              float t = tanhf(xn.w + r * hn.w); hv.w = (1.f - z) * t + z * ho.w; }
            Hs[m] = hv;
        }
        __syncthreads();
    }
}

// ---------------- decoder stage 1: d1 = leaky_relu(hemb @ W_d1^T + b_d1) ----------------
__global__ void __launch_bounds__(NP1) d1_kernel() {
    __shared__ float4 Xs[E_];
    int tid = threadIdx.x;
    int i0 = blockIdx.x * 4;
    if (tid < E_) {
        float4 v;
        v.x = g_hemb[(size_t)(i0 + 0) * E_ + tid];
        v.y = g_hemb[(size_t)(i0 + 1) * E_ + tid];
        v.z = g_hemb[(size_t)(i0 + 2) * E_ + tid];
        v.w = g_hemb[(size_t)(i0 + 3) * E_ + tid];
        Xs[tid] = v;
    }
    __syncthreads();
    int n = tid;
    float bv = g_bd1_pad[n];
    float a0 = bv, a1 = bv, a2 = bv, a3 = bv;
#pragma unroll 5
    for (int kk = 0; kk < E_; kk++) {
        float w = g_Wd1T[kk * NP1 + n];
        float4 x = Xs[kk];
        a0 = fmaf(w, x.x, a0); a1 = fmaf(w, x.y, a1);
        a2 = fmaf(w, x.z, a2); a3 = fmaf(w, x.w, a3);
    }
    a0 = a0 >= 0.f ? a0 : 0.01f * a0;
    a1 = a1 >= 0.f ? a1 : 0.01f * a1;
    a2 = a2 >= 0.f ? a2 : 0.01f * a2;
    a3 = a3 >= 0.f ? a3 : 0.01f * a3;
    if (n < E_) {
        g_d1[(size_t)(i0 + 0) * E_ + n] = a0;
        g_d1[(size_t)(i0 + 1) * E_ + n] = a1;
        g_d1[(size_t)(i0 + 2) * E_ + n] = a2;
        g_d1[(size_t)(i0 + 3) * E_ + n] = a3;
    }
}

// ---------------- decoder stage 2: logits over compacted valid rows ----------------
#define AS4 9   // A_s row stride in float4 (36 floats)
__global__ void __launch_bounds__(256) logits_kernel(const float* __restrict__ bd2,
                                                     float* __restrict__ out) {
    __shared__ float4 A_s4[E_ * AS4];
    __shared__ int rows_s[32];
    float* A_s = (float*)A_s4;
    int tid = threadIdx.x;
    int i0 = blockIdx.x * 32;                 // tile over compacted rows
    int nv = g_nvalid;
    if (i0 >= nv) return;
    int nrows = nv - i0; if (nrows > 32) nrows = 32;
    int vt = blockIdx.y * 256;                // v tile

    if (tid < 32) rows_s[tid] = (tid < nrows) ? g_rows[i0 + tid] : -1;
    __syncthreads();

    for (int idx = tid; idx < 32 * E_; idx += 256) {
        int r = idx / E_, kk = idx - r * E_;
        A_s[kk * 36 + r] = (r < nrows) ? g_d1[(size_t)rows_s[r] * E_ + kk] : 0.f;
    }
    __syncthreads();

    int vq = vt + (tid & 63) * 4;
    int g2 = (tid >> 6) * 2;
    int rb = (tid >> 6) * 8;
    float4 acc[8];
#pragma unroll
    for (int r = 0; r < 8; r++) acc[r] = make_float4(0.f, 0.f, 0.f, 0.f);

    if (vq < V_) {
#pragma unroll 2
        for (int kk = 0; kk < E_; kk++) {
            float4 w = *(const float4*)&g_Wd2T[(size_t)kk * VP + vq];
            float4 xa = A_s4[kk * AS4 + g2];
            float4 xb = A_s4[kk * AS4 + g2 + 1];
            float ar[8] = {xa.x, xa.y, xa.z, xa.w, xb.x, xb.y, xb.z, xb.w};
#pragma unroll
            for (int r = 0; r < 8; r++) {
                acc[r].x = fmaf(ar[r], w.x, acc[r].x);
                acc[r].y = fmaf(ar[r], w.y, acc[r].y);
                acc[r].z = fmaf(ar[r], w.z, acc[r].z);
                acc[r].w = fmaf(ar[r], w.w, acc[r].w);
            }
        }
        float4 bb = *(const float4*)&bd2[vq];
#pragma unroll
        for (int r = 0; r < 8; r++) {
            if (rb + r < nrows) {
                int i = rows_s[rb + r];
                int kk = i >> 9, b = i & 511;
                float4 o = make_float4(acc[r].x + bb.x, acc[r].y + bb.y,
                                       acc[r].z + bb.z, acc[r].w + bb.w);
                *(float4*)&out[((size_t)b * (T_ - 1) + kk) * V_ + vq] = o;
            }
        }
    }
}

// ---------------- launch ----------------
extern "C" void kernel_launch(void* const* d_in, const int* in_sizes, int n_in,
                              void* d_out, int out_size) {
    (void)in_sizes; (void)n_in; (void)out_size;
    const float* codes   = (const float*)d_in[1];
    const int*   lengths = (const int*)d_in[2];
    const float* W_emb   = (const float*)d_in[3];
    const float* b_emb   = (const float*)d_in[4];
    const float* W1      = (const float*)d_in[5];
    const float* W2      = (const float*)d_in[6];
    const float* W3      = (const float*)d_in[7];
    const float* W_u     = (const float*)d_in[8];
    const float* b_u     = (const float*)d_in[9];
    const float* W_ih    = (const float*)d_in[10];
    const float* W_hh    = (const float*)d_in[11];
    const float* b_ih    = (const float*)d_in[12];
    const float* b_hh    = (const float*)d_in[13];
    const float* W_d1    = (const float*)d_in[14];
    const float* b_d1    = (const float*)d_in[15];
    const float* W_d2    = (const float*)d_in[16];
    const float* b_d2    = (const float*)d_in[17];
    float* out = (float*)d_out;

    // seq_kernel stays my launch #4 (= overall #6 for ncu -s 5 -c 1).
    prep_wemb<<<(V_ * E_ + 255) / 256, 256>>>(W_emb);                          // 1
    prep_all<<<(E_ * NP1 + 255) / 256, 256>>>(W1, W2, W3, W_u, b_u,
                                              W_ih, W_hh, W_d1, b_d1);         // 2
    embed_kernel<<<B_ * T_, 256>>>(codes, b_emb);                              // 3
    seq_kernel<<<B_ / 4, 2 * HP>>>(b_ih, b_hh);                                // 4 <- profiled
    prep_wd2<<<(E_ * VP + 255) / 256, 256>>>(W_d2);                            // 5
    prep_len<<<2, 256>>>(lengths);                                             // 6
    rowlist_kernel<<<1, 1024>>>();                                             // 7
    d1_kernel<<<NROWS / 4, NP1>>>();                                           // 8
    zerofill_kernel<<<NROWS, 256>>>(out);                                      // 9
    dim3 lgrid((NROWS + 31) / 32, (V_ + 255) / 256);
    logits_kernel<<<lgrid, 256>>>(b_d2, out);                                  // 10
}

// round 17
// speedup vs baseline: 2.1209x; 1.0238x over previous
#include <cuda_runtime.h>
#include <math.h>

#define B_  512
#define T_  24
#define V_  8000
#define E_  300
#define M_  30
#define H_  330
#define HP  352            // padded n-columns (11 warps)
#define NSTEPS 8
#define DT_ 0.875f         // 7/8
#define VP  8192           // padded V for W_d2T
#define NP1 320            // padded N for d1 stage
#define NQ  84             // k-quads per matrix (K padded to 336)
#define QH  42             // quads per k-half
#define NGR 7              // pipeline groups per half (42 = 7 * 6)
#define NROWS ((T_ - 1) * B_)   // 11776 decoder rows

// ---------------- device scratch (static, no allocation) ----------------
__device__ float4 g_W4ode[3 * NQ * HP];  // [mat][q][n] quad = W[4q..4q+3][n]
__device__ float4 g_W4u[NQ * HP];        // Wu quads
__device__ float g_WihT[E_ * 96];        // [e<300][g<90]
__device__ float g_WhhT[M_ * 96];        // [m<30][g<90]
__device__ float g_Wd1T[E_ * NP1];       // [k<300][n<300]
__device__ float g_Wd2T[E_ * VP];        // [n<300][v<8000]
__device__ float g_WembT[V_ * E_];       // [v][e]
__device__ float g_bu_pad[HP];
__device__ float g_bd1_pad[NP1];
__device__ int   g_len[B_];
__device__ int   g_rows[NROWS];          // compacted valid decoder rows
__device__ int   g_nvalid;
__device__ float g_gall[(size_t)B_ * T_ * E_];        // [b][t][e]
__device__ float g_hemb[(size_t)NROWS * E_];          // [kk][b][e]
__device__ float g_d1[(size_t)NROWS * E_];            // [kk][b][e]

// ---------------- f32x2 packed-math helpers (sm_10x) ----------------
__device__ __forceinline__ unsigned long long dup2(float w) {
    unsigned long long r;
    asm("mov.b64 %0, {%1, %1};" : "=l"(r) : "f"(w));
    return r;
}
__device__ __forceinline__ void ffma2(unsigned long long& acc,
                                      unsigned long long w2, unsigned long long x2) {
    asm("fma.rn.f32x2 %0, %1, %2, %0;" : "+l"(acc) : "l"(w2), "l"(x2));
}
__device__ __forceinline__ unsigned long long add2(unsigned long long a,
                                                   unsigned long long b) {
    unsigned long long r;
    asm("add.rn.f32x2 %0, %1, %2;" : "=l"(r) : "l"(a), "l"(b));
    return r;
}
__device__ __forceinline__ float2 unpack2(unsigned long long v) {
    float lo, hi;
    asm("mov.b64 {%0, %1}, %2;" : "=f"(lo), "=f"(hi) : "l"(v));
    return make_float2(lo, hi);
}

// ---------------- lengths normalization (int32 vs int64 auto-detect) ----------------
__global__ void prep_len(const int* __restrict__ Lraw) {
    int b = blockIdx.x * blockDim.x + threadIdx.x;
    if (b >= B_) return;
    int is64 = (Lraw[1] == 0);
    g_len[b] = is64 ? Lraw[2 * b] : Lraw[b];
}

// ---------------- compacted valid-row list (deterministic scan) ----------------
__global__ void __launch_bounds__(1024) rowlist_kernel() {
    __shared__ int cnts[1024];
    int t = threadIdx.x;
    int lo = t * 12, hi = lo + 12;
    if (hi > NROWS) hi = NROWS;
    int c = 0;
    for (int i = lo; i < hi; i++) {
        int kk = i >> 9, b = i & 511;
        if ((kk + 1) < g_len[b]) c++;
    }
    cnts[t] = c;
    __syncthreads();
    for (int off = 1; off < 1024; off <<= 1) {
        int val = cnts[t];
        int add = (t >= off) ? cnts[t - off] : 0;
        __syncthreads();
        cnts[t] = val + add;
        __syncthreads();
    }
    int p = cnts[t] - c;
    for (int i = lo; i < hi; i++) {
        int kk = i >> 9, b = i & 511;
        if ((kk + 1) < g_len[b]) g_rows[p++] = i;
    }
    if (t == 1023) g_nvalid = cnts[1023];
}

// ---------------- zero-fill invalid decoder rows ----------------
__global__ void __launch_bounds__(256) zerofill_kernel(float* __restrict__ out) {
    int i = blockIdx.x;
    int kk = i >> 9, b = i & 511;
    if ((kk + 1) < g_len[b]) return;
    float4* row = (float4*)(out + ((size_t)b * (T_ - 1) + kk) * V_);
    const float4 z = make_float4(0.f, 0.f, 0.f, 0.f);
    for (int j = threadIdx.x; j < V_ / 4; j += 256) row[j] = z;
}

// ---------------- fused weight prep ----------------
__global__ void prep_all(const float* __restrict__ W1, const float* __restrict__ W2,
                         const float* __restrict__ W3, const float* __restrict__ Wu,
                         const float* __restrict__ bu,
                         const float* __restrict__ Wih, const float* __restrict__ Whh,
                         const float* __restrict__ Wd1, const float* __restrict__ bd1) {
    int i = blockIdx.x * blockDim.x + threadIdx.x;
    if (i < 3 * NQ * HP) {
        int mat = i / (NQ * HP);
        int r = i - mat * (NQ * HP);
        int q = r / HP, n = r % HP;
        const float* W = (mat == 0) ? W1 : (mat == 1) ? W2 : W3;
        float4 v = make_float4(0.f, 0.f, 0.f, 0.f);
        if (n < H_) {
            int k = 4 * q;
            if (k + 0 < H_) v.x = W[n * H_ + k + 0];
            if (k + 1 < H_) v.y = W[n * H_ + k + 1];
            if (k + 2 < H_) v.z = W[n * H_ + k + 2];
            if (k + 3 < H_) v.w = W[n * H_ + k + 3];
        }
        g_W4ode[i] = v;
    }
    if (i < NQ * HP) {
        int q = i / HP, n = i % HP;
        float4 v = make_float4(0.f, 0.f, 0.f, 0.f);
        if (n < E_) {
            int k = 4 * q;
            if (k + 0 < H_) v.x = Wu[n * H_ + k + 0];
            if (k + 1 < H_) v.y = Wu[n * H_ + k + 1];
            if (k + 2 < H_) v.z = Wu[n * H_ + k + 2];
            if (k + 3 < H_) v.w = Wu[n * H_ + k + 3];
        }
        g_W4u[i] = v;
    }
    if (i < E_ * 96) {
        int e = i / 96, g = i % 96;
        g_WihT[i] = (g < 90) ? Wih[g * E_ + e] : 0.f;
    }
    if (i < M_ * 96) {
        int m = i / 96, g = i % 96;
        g_WhhT[i] = (g < 90) ? Whh[g * M_ + m] : 0.f;
    }
    if (i < E_ * NP1) {
        int k = i / NP1, n = i % NP1;
        g_Wd1T[i] = (n < E_) ? Wd1[n * E_ + k] : 0.f;
    }
    if (i < HP)  g_bu_pad[i]  = (i < E_) ? bu[i]  : 0.f;
    if (i < NP1) g_bd1_pad[i] = (i < E_) ? bd1[i] : 0.f;
}

__global__ void prep_wd2(const float* __restrict__ Wd2) {
    int i = blockIdx.x * blockDim.x + threadIdx.x;
    if (i >= E_ * VP) return;
    int n = i / VP, v = i % VP;
    g_Wd2T[i] = (v < V_) ? Wd2[v * E_ + n] : 0.f;
}

__global__ void prep_wemb(const float* __restrict__ Wemb) {
    int i = blockIdx.x * blockDim.x + threadIdx.x;
    if (i >= V_ * E_) return;
    int v = i / E_, e = i % E_;
    g_WembT[i] = Wemb[e * V_ + v];
}

// ---------------- sparse embedding (deterministic prefix-scan compaction) ----------------
__global__ void __launch_bounds__(256) embed_kernel(const float* __restrict__ codes,
                                                    const float* __restrict__ bemb) {
    __shared__ int idx[1024];
    __shared__ int cnts[256];
    __shared__ int total;
    int blk = blockIdx.x;               // blk = b*T_ + t
    int t = threadIdx.x;
    const float* crow = codes + (size_t)blk * V_;
    int base = t * 32;
    int c = 0;
#pragma unroll 4
    for (int j = 0; j < 32; j++) {
        int v = base + j;
        if (v < V_ && crow[v] != 0.f) c++;
    }
    cnts[t] = c;
    __syncthreads();
    for (int off = 1; off < 256; off <<= 1) {
        int val = cnts[t];
        int add = (t >= off) ? cnts[t - off] : 0;
        __syncthreads();
        cnts[t] = val + add;
        __syncthreads();
    }
    int p = cnts[t] - c;
    for (int j = 0; j < 32; j++) {
        int v = base + j;
        if (v < V_ && crow[v] != 0.f) {
            if (p < 1024) idx[p] = v;
            p++;
        }
    }
    if (t == 255) total = cnts[255];
    __syncthreads();
    int n = total > 1024 ? 1024 : total;
    for (int e = t; e < E_; e += 256) {
        float acc = bemb[e];
        for (int j = 0; j < n; j++) acc += g_WembT[idx[j] * E_ + e];
        g_gall[(size_t)blk * E_ + e] = acc;
    }
}

// ---------------- sequential ODE + GRU kernel (704 threads, split-K(2), f32x2) ----------------
__device__ __forceinline__ void grp_fma6(const float4* __restrict__ wb,
                                         const float4* __restrict__ xp,
                                         unsigned long long& a01,
                                         unsigned long long& a23) {
#pragma unroll
    for (int j = 0; j < 6; j++) {
        float4 w = wb[j];
        const ulonglong2* xq = reinterpret_cast<const ulonglong2*>(xp + 4 * j);
        ulonglong2 x0 = xq[0], x1 = xq[1], x2 = xq[2], x3 = xq[3];
        unsigned long long wx = dup2(w.x), wy = dup2(w.y);
        unsigned long long wz = dup2(w.z), ww = dup2(w.w);
        ffma2(a01, wx, x0.x); ffma2(a23, wx, x0.y);
        ffma2(a01, wy, x1.x); ffma2(a23, wy, x1.y);
        ffma2(a01, wz, x2.x); ffma2(a23, wz, x2.y);
        ffma2(a01, ww, x3.x); ffma2(a23, ww, x3.y);
    }
}

// Split-K matmul stage: kh half owns 42 quads (7 ping-pong groups of 6),
// rotated per warp (g0). kh=1 deposits packed partials; kh=0 combines.
template <bool TANH, bool BIAS>
__device__ __forceinline__ void mm2(const float4* __restrict__ W4,
                                    const float4* __restrict__ xs,
                                    float4* __restrict__ ys,
                                    float4* __restrict__ part,
                                    const float* __restrict__ bias,
                                    int n, int kh, int g0) {
    unsigned long long a01 = 0ull, a23 = 0ull;
    const float4* wk = W4 + (size_t)(kh * QH) * HP + n;
    const float4* xk = xs + kh * (QH * 4);
    float4 wA[6], wB[6];
    int g = g0;
    {
        const float4* p = wk + (size_t)(g * 6) * HP;
#pragma unroll
        for (int j = 0; j < 6; j++) wA[j] = p[j * HP];
    }
#pragma unroll 1
    for (int it = 0; it < 3; it++) {
        int g1 = g + 1; if (g1 >= NGR) g1 = 0;
        {
            const float4* p = wk + (size_t)(g1 * 6) * HP;
#pragma unroll
            for (int j = 0; j < 6; j++) wB[j] = p[j * HP];
        }
        grp_fma6(wA, xk + 24 * g, a01, a23);
        int g2 = g1 + 1; if (g2 >= NGR) g2 = 0;
        {
            const float4* p = wk + (size_t)(g2 * 6) * HP;
#pragma unroll
            for (int j = 0; j < 6; j++) wA[j] = p[j * HP];
        }
        grp_fma6(wB, xk + 24 * g1, a01, a23);
        g = g2;
    }
    grp_fma6(wA, xk + 24 * g, a01, a23);
    if (kh) {
        ulonglong2 pv; pv.x = a01; pv.y = a23;
        *reinterpret_cast<ulonglong2*>(&part[n]) = pv;
    }
    __syncthreads();
    if (!kh) {
        ulonglong2 pv = *reinterpret_cast<const ulonglong2*>(&part[n]);
        a01 = add2(a01, pv.x);
        a23 = add2(a23, pv.y);
        float2 f01 = unpack2(a01), f23 = unpack2(a23);
        float a0 = f01.x, a1 = f01.y, a2 = f23.x, a3 = f23.y;
        if (BIAS) { float bv = bias[n]; a0 += bv; a1 += bv; a2 += bv; a3 += bv; }
        if (TANH) { a0 = tanhf(a0); a1 = tanhf(a1); a2 = tanhf(a2); a3 = tanhf(a3); }
        ys[n] = make_float4(a0, a1, a2, a3);
    }
    __syncthreads();
}

__device__ __forceinline__ void ode_f(const float4* src, float4* bufA, float4* bufB,
                                      float4* part, int n, int kh, int g0) {
    mm2<true, false>(g_W4ode,               src,  bufA, part, nullptr, n, kh, g0);
    mm2<true, false>(g_W4ode + NQ * HP,     bufA, bufB, part, nullptr, n, kh, g0);
    mm2<true, false>(g_W4ode + 2 * NQ * HP, bufB, bufA, part, nullptr, n, kh, g0);
}

__device__ __forceinline__ float sigf(float x) { return 1.f / (1.f + expf(-x)); }

__global__ void __launch_bounds__(2 * HP, 1) seq_kernel(const float* __restrict__ b_ih,
                                                        const float* __restrict__ b_hh) {
    __shared__ float4 Hs[HP], ACC[HP], Ys[HP], As[HP], Bs[HP], Ps[HP];
    __shared__ float4 G1[96], G2[96];
    int tid = threadIdx.x;
    int kh = tid >= HP;
    int n  = tid - kh * HP;
    int b0 = blockIdx.x * 4;
    int g0 = (blockIdx.x * 22 + (tid >> 5)) % NGR;    // per-warp rotation phase

    // h0 = [zeros(M), g_all[:,0,:]]
    if (!kh) {
        float4 h = make_float4(0.f, 0.f, 0.f, 0.f);
        if (n >= M_ && n < H_) {
            int e = n - M_;
            h.x = g_gall[((size_t)(b0 + 0) * T_ + 0) * E_ + e];
            h.y = g_gall[((size_t)(b0 + 1) * T_ + 0) * E_ + e];
            h.z = g_gall[((size_t)(b0 + 2) * T_ + 0) * E_ + e];
            h.w = g_gall[((size_t)(b0 + 3) * T_ + 0) * E_ + e];
        }
        Hs[n] = h;
    }
    __syncthreads();

    for (int k = 1; k < T_; k++) {
        // ---- RK4 with N_STEPS substeps ----
        for (int s = 0; s < NSTEPS; s++) {
            ode_f(Hs, As, Bs, Ps, n, kh, g0);                    // k1 -> As
            if (!kh) {
                float4 a = As[n], h = Hs[n];
                ACC[n] = a;
                Ys[n] = make_float4(h.x + 0.5f * DT_ * a.x, h.y + 0.5f * DT_ * a.y,
                                    h.z + 0.5f * DT_ * a.z, h.w + 0.5f * DT_ * a.w);
            }
            __syncthreads();
            ode_f(Ys, As, Bs, Ps, n, kh, g0);                    // k2 -> As
            if (!kh) {
                float4 a = As[n], h = Hs[n], c = ACC[n];
                ACC[n] = make_float4(c.x + 2.f * a.x, c.y + 2.f * a.y,
                                     c.z + 2.f * a.z, c.w + 2.f * a.w);
                Ys[n] = make_float4(h.x + 0.5f * DT_ * a.x, h.y + 0.5f * DT_ * a.y,
                                    h.z + 0.5f * DT_ * a.z, h.w + 0.5f * DT_ * a.w);
            }
            __syncthreads();
            ode_f(Ys, As, Bs, Ps, n, kh, g0);                    // k3 -> As
            if (!kh) {
                float4 a = As[n], h = Hs[n], c = ACC[n];
                ACC[n] = make_float4(c.x + 2.f * a.x, c.y + 2.f * a.y,
                                     c.z + 2.f * a.z, c.w + 2.f * a.w);
                Ys[n] = make_float4(h.x + DT_ * a.x, h.y + DT_ * a.y,
                                    h.z + DT_ * a.z, h.w + DT_ * a.w);
            }
            __syncthreads();
            ode_f(Ys, As, Bs, Ps, n, kh, g0);                    // k4 -> As
            if (!kh) {
                const float c6 = DT_ / 6.f;
                float4 a = As[n], h = Hs[n], c = ACC[n];
                Hs[n] = make_float4(h.x + c6 * (c.x + a.x), h.y + c6 * (c.y + a.y),
                                    h.z + c6 * (c.z + a.z), h.w + c6 * (c.w + a.w));
            }
            __syncthreads();
        }

        // ---- dump h_emb for the decoupled decoder; build cin = [h_mem, g_k] ----
        if (!kh) {
            if (n < E_) {
                float4 v = Hs[M_ + n];
                size_t base = ((size_t)(k - 1) * B_ + b0) * E_ + n;
                g_hemb[base]          = v.x;
                g_hemb[base + E_]     = v.y;
                g_hemb[base + 2 * E_] = v.z;
                g_hemb[base + 3 * E_] = v.w;
            }
            float4 c = make_float4(0.f, 0.f, 0.f, 0.f);
            if (n < M_) c = Hs[n];
            else if (n < H_) {
                int e = n - M_;
                c.x = g_gall[((size_t)(b0 + 0) * T_ + k) * E_ + e];
                c.y = g_gall[((size_t)(b0 + 1) * T_ + k) * E_ + e];
                c.z = g_gall[((size_t)(b0 + 2) * T_ + k) * E_ + e];
                c.w = g_gall[((size_t)(b0 + 3) * T_ + k) * E_ + e];
            }
            Ys[n] = c;
        }
        __syncthreads();

        // ---- x = cin @ W_u^T + b_u  -> As ----
        mm2<false, true>(g_W4u, Ys, As, Ps, g_bu_pad, n, kh, g0);

        // ---- GRU gates (low warps; inputs ready after mm2's final barrier) ----
        if (tid < 96) {
            int g = tid;
            float bb = (g < 90) ? b_ih[g] : 0.f;
            float4 a = make_float4(bb, bb, bb, bb);
#pragma unroll 4
            for (int e = 0; e < E_; e++) {
                float w = g_WihT[e * 96 + g];
                float4 x = As[e];
                a.x = fmaf(w, x.x, a.x); a.y = fmaf(w, x.y, a.y);
                a.z = fmaf(w, x.z, a.z); a.w = fmaf(w, x.w, a.w);
            }
            G1[g] = a;
        } else if (tid < 192) {
            int g = tid - 96;
            float bb = (g < 90) ? b_hh[g] : 0.f;
            float4 a = make_float4(bb, bb, bb, bb);
#pragma unroll
            for (int m = 0; m < M_; m++) {
                float w = g_WhhT[m * 96 + g];
                float4 x = Hs[m];
                a.x = fmaf(w, x.x, a.x); a.y = fmaf(w, x.y, a.y);
                a.z = fmaf(w, x.z, a.z); a.w = fmaf(w, x.w, a.w);
            }
            G2[g] = a;
        }
        __syncthreads();

        if (tid < M_) {
            int m = tid;
            float4 xr = G1[m],          hr = G2[m];
            float4 xz = G1[M_ + m],     hz = G2[M_ + m];
            float4 xn = G1[2 * M_ + m], hn = G2[2 * M_ + m];
            float4 ho = Hs[m];
            float4 hv;
            { float r = sigf(xr.x + hr.x), z = sigf(xz.x + hz.x);
              float t = tanhf(xn.x + r * hn.x); hv.x = (1.f - z) * t + z * ho.x; }
            { float r = sigf(xr.y + hr.y), z = sigf(xz.y + hz.y);
              float t = tanhf(xn.y + r * hn.y); hv.y = (1.f - z) * t + z * ho.y; }
            { float r = sigf(xr.z + hr.z), z = sigf(xz.z + hz.z);
              float t = tanhf(xn.z + r * hn.z); hv.z = (1.f - z) * t + z * ho.z; }
            { float r = sigf(xr.w + hr.w), z = sigf(xz.w + hz.w);
              float t = tanhf(xn.w + r * hn.w); hv.w = (1.f - z) * t + z * ho.w; }
            Hs[m] = hv;
        }
        __syncthreads();
    }
}

// ---------------- decoder stage 1: d1 = leaky_relu(hemb @ W_d1^T + b_d1) ----------------
__global__ void __launch_bounds__(NP1) d1_kernel() {
    __shared__ float4 Xs[E_];
    int tid = threadIdx.x;
    int i0 = blockIdx.x * 4;
    if (tid < E_) {
        float4 v;
        v.x = g_hemb[(size_t)(i0 + 0) * E_ + tid];
        v.y = g_hemb[(size_t)(i0 + 1) * E_ + tid];
        v.z = g_hemb[(size_t)(i0 + 2) * E_ + tid];
        v.w = g_hemb[(size_t)(i0 + 3) * E_ + tid];
        Xs[tid] = v;
    }
    __syncthreads();
    int n = tid;
    float bv = g_bd1_pad[n];
    float a0 = bv, a1 = bv, a2 = bv, a3 = bv;
#pragma unroll 5
    for (int kk = 0; kk < E_; kk++) {
        float w = g_Wd1T[kk * NP1 + n];
        float4 x = Xs[kk];
        a0 = fmaf(w, x.x, a0); a1 = fmaf(w, x.y, a1);
        a2 = fmaf(w, x.z, a2); a3 = fmaf(w, x.w, a3);
    }
    a0 = a0 >= 0.f ? a0 : 0.01f * a0;
    a1 = a1 >= 0.f ? a1 : 0.01f * a1;
    a2 = a2 >= 0.f ? a2 : 0.01f * a2;
    a3 = a3 >= 0.f ? a3 : 0.01f * a3;
    if (n < E_) {
        g_d1[(size_t)(i0 + 0) * E_ + n] = a0;
        g_d1[(size_t)(i0 + 1) * E_ + n] = a1;
        g_d1[(size_t)(i0 + 2) * E_ + n] = a2;
        g_d1[(size_t)(i0 + 3) * E_ + n] = a3;
    }
}

// ---------------- decoder stage 2: logits over compacted valid rows ----------------
#define AS4 9   // A_s row stride in float4 (36 floats)
__global__ void __launch_bounds__(256) logits_kernel(const float* __restrict__ bd2,
                                                     float* __restrict__ out) {
    __shared__ float4 A_s4[E_ * AS4];
    __shared__ int rows_s[32];
    float* A_s = (float*)A_s4;
    int tid = threadIdx.x;
    int i0 = blockIdx.x * 32;                 // tile over compacted rows
    int nv = g_nvalid;
    if (i0 >= nv) return;
    int nrows = nv - i0; if (nrows > 32) nrows = 32;
    int vt = blockIdx.y * 256;                // v tile

    if (tid < 32) rows_s[tid] = (tid < nrows) ? g_rows[i0 + tid] : -1;
    __syncthreads();

    for (int idx = tid; idx < 32 * E_; idx += 256) {
        int r = idx / E_, kk = idx - r * E_;
        A_s[kk * 36 + r] = (r < nrows) ? g_d1[(size_t)rows_s[r] * E_ + kk] : 0.f;
    }
    __syncthreads();

    int vq = vt + (tid & 63) * 4;
    int g2 = (tid >> 6) * 2;
    int rb = (tid >> 6) * 8;
    float4 acc[8];
#pragma unroll
    for (int r = 0; r < 8; r++) acc[r] = make_float4(0.f, 0.f, 0.f, 0.f);

    if (vq < V_) {
#pragma unroll 2
        for (int kk = 0; kk < E_; kk++) {
            float4 w = *(const float4*)&g_Wd2T[(size_t)kk * VP + vq];
            float4 xa = A_s4[kk * AS4 + g2];
            float4 xb = A_s4[kk * AS4 + g2 + 1];
            float ar[8] = {xa.x, xa.y, xa.z, xa.w, xb.x, xb.y, xb.z, xb.w};
#pragma unroll
            for (int r = 0; r < 8; r++) {
                acc[r].x = fmaf(ar[r], w.x, acc[r].x);
                acc[r].y = fmaf(ar[r], w.y, acc[r].y);
                acc[r].z = fmaf(ar[r], w.z, acc[r].z);
                acc[r].w = fmaf(ar[r], w.w, acc[r].w);
            }
        }
        float4 bb = *(const float4*)&bd2[vq];
#pragma unroll
        for (int r = 0; r < 8; r++) {
            if (rb + r < nrows) {
                int i = rows_s[rb + r];
                int kk = i >> 9, b = i & 511;
                float4 o = make_float4(acc[r].x + bb.x, acc[r].y + bb.y,
                                       acc[r].z + bb.z, acc[r].w + bb.w);
                *(float4*)&out[((size_t)b * (T_ - 1) + kk) * V_ + vq] = o;
            }
        }
    }
}

// ---------------- launch ----------------
extern "C" void kernel_launch(void* const* d_in, const int* in_sizes, int n_in,
                              void* d_out, int out_size) {
    (void)in_sizes; (void)n_in; (void)out_size;
    const float* codes   = (const float*)d_in[1];
    const int*   lengths = (const int*)d_in[2];
    const float* W_emb   = (const float*)d_in[3];
    const float* b_emb   = (const float*)d_in[4];
    const float* W1      = (const float*)d_in[5];
    const float* W2      = (const float*)d_in[6];
    const float* W3      = (const float*)d_in[7];
    const float* W_u     = (const float*)d_in[8];
    const float* b_u     = (const float*)d_in[9];
    const float* W_ih    = (const float*)d_in[10];
    const float* W_hh    = (const float*)d_in[11];
    const float* b_ih    = (const float*)d_in[12];
    const float* b_hh    = (const float*)d_in[13];
    const float* W_d1    = (const float*)d_in[14];
    const float* b_d1    = (const float*)d_in[15];
    const float* W_d2    = (const float*)d_in[16];
    const float* b_d2    = (const float*)d_in[17];
    float* out = (float*)d_out;

    // seq_kernel stays my launch #4 (= overall #6 for ncu -s 5 -c 1).
    prep_wemb<<<(V_ * E_ + 255) / 256, 256>>>(W_emb);                          // 1
    prep_all<<<(E_ * NP1 + 255) / 256, 256>>>(W1, W2, W3, W_u, b_u,
                                              W_ih, W_hh, W_d1, b_d1);         // 2
    embed_kernel<<<B_ * T_, 256>>>(codes, b_emb);                              // 3
    seq_kernel<<<B_ / 4, 2 * HP>>>(b_ih, b_hh);                                // 4 <- profiled
    prep_wd2<<<(E_ * VP + 255) / 256, 256>>>(W_d2);                            // 5
    prep_len<<<2, 256>>>(lengths);                                             // 6
    rowlist_kernel<<<1, 1024>>>();                                             // 7
    d1_kernel<<<NROWS / 4, NP1>>>();                                           // 8
    zerofill_kernel<<<NROWS, 256>>>(out);                                      // 9
    dim3 lgrid((NROWS + 31) / 32, (V_ + 255) / 256);
    logits_kernel<<<lgrid, 256>>>(b_d2, out);                                  // 10
}